// round 15
// speedup vs baseline: 6.4505x; 1.0284x over previous
#include <cuda_runtime.h>
#include <cuda_bf16.h>
#include <math.h>
#include <stdint.h>

#define B_    4
#define NTOK  8192
#define D_    512
#define H_    8
#define DH_   64
#define MLM   256
#define LSEG  32
#define BH    (B_*H_)
#define KER_  33
#define NCHK  8
#define A1_TPB 4

__device__ __forceinline__ uint32_t smem_to_u32(const void* p) {
    uint32_t a;
    asm("{ .reg .u64 t; cvta.to.shared.u64 t, %1; cvt.u32.u64 %0, t; }" : "=r"(a) : "l"(p));
    return a;
}
__device__ __forceinline__ void cp_async16(uint32_t saddr, const void* gptr) {
    asm volatile("cp.async.cg.shared.global [%0], [%1], 16;" :: "r"(saddr), "l"(gptr));
}
#define CP_COMMIT() asm volatile("cp.async.commit_group;" ::: "memory")
#define CP_WAIT0()  asm volatile("cp.async.wait_group 0;" ::: "memory")
__device__ __forceinline__ void mma_bf16p(float (&d)[4], const uint32_t (&a)[4], uint32_t b0, uint32_t b1) {
    asm volatile("mma.sync.aligned.m16n8k16.row.col.f32.bf16.bf16.f32 "
        "{%0,%1,%2,%3}, {%4,%5,%6,%7}, {%8,%9}, {%0,%1,%2,%3};"
        : "+f"(d[0]), "+f"(d[1]), "+f"(d[2]), "+f"(d[3])
        : "r"(a[0]), "r"(a[1]), "r"(a[2]), "r"(a[3]), "r"(b0), "r"(b1));
}
__device__ __forceinline__ void ldsm4(uint32_t (&r)[4], uint32_t a) {
    asm volatile("ldmatrix.sync.aligned.m8n8.x4.shared.b16 {%0,%1,%2,%3}, [%4];"
        : "=r"(r[0]), "=r"(r[1]), "=r"(r[2]), "=r"(r[3]) : "r"(a));
}
__device__ __forceinline__ float fexp(float s) {
    float t = s * 1.44269504088896341f;
    float i = rintf(t);
    float f = t - i;
    float p = 1.54035303933816e-4f;
    p = p * f + 1.33335581464284e-3f;
    p = p * f + 9.61812910762848e-3f;
    p = p * f + 5.55041086648216e-2f;
    p = p * f + 2.40226506959101e-1f;
    p = p * f + 6.93147180559945e-1f;
    p = p * f + 1.0f;
    return p * __int_as_float(((int)i + 127) << 23);
}

// scratch
__device__ __nv_bfloat16 g_nh[(size_t)B_*NTOK*D_];
__device__ __nv_bfloat16 g_nl[(size_t)B_*NTOK*D_];
__device__ __nv_bfloat16 g_wqh[(size_t)3*D_*D_];
__device__ __nv_bfloat16 g_wql[(size_t)3*D_*D_];
__device__ __nv_bfloat16 g_woh[(size_t)D_*D_];
__device__ __nv_bfloat16 g_wol[(size_t)D_*D_];
__device__ __nv_bfloat16 g_Oh[(size_t)B_*NTOK*D_];
__device__ __nv_bfloat16 g_Ol[(size_t)B_*NTOK*D_];
__device__ float g_q [(size_t)BH*NTOK*DH_];
__device__ float g_k [(size_t)BH*NTOK*DH_];
__device__ float g_v [(size_t)BH*NTOK*DH_];
__device__ __nv_bfloat16 g_qbh[(size_t)BH*NTOK*DH_];
__device__ __nv_bfloat16 g_qbl[(size_t)BH*NTOK*DH_];
__device__ __nv_bfloat16 g_kbh[(size_t)BH*NTOK*DH_];
__device__ __nv_bfloat16 g_kbl[(size_t)BH*NTOK*DH_];
__device__ __nv_bfloat16 g_vth[(size_t)BH*NTOK*DH_];
__device__ __nv_bfloat16 g_vtl[(size_t)BH*NTOK*DH_];
__device__ float g_ql[(size_t)BH*MLM*DH_];
__device__ float g_kl[(size_t)BH*MLM*DH_];
__device__ __nv_bfloat16 g_qlh[(size_t)BH*MLM*DH_];
__device__ __nv_bfloat16 g_qll[(size_t)BH*MLM*DH_];
__device__ __nv_bfloat16 g_klh[(size_t)BH*MLM*DH_];
__device__ __nv_bfloat16 g_kll[(size_t)BH*MLM*DH_];
__device__ __nv_bfloat16 g_yth[(size_t)BH*MLM*DH_];
__device__ __nv_bfloat16 g_ytl[(size_t)BH*MLM*DH_];
__device__ float g_X [(size_t)BH*MLM*MLM];
__device__ __nv_bfloat16 g_Xh[(size_t)BH*MLM*MLM];
__device__ __nv_bfloat16 g_Xl[(size_t)BH*MLM*MLM];
__device__ __nv_bfloat16 g_Znh[2][(size_t)BH*MLM*MLM];
__device__ __nv_bfloat16 g_Znl[2][(size_t)BH*MLM*MLM];
__device__ __nv_bfloat16 g_Zth[2][(size_t)BH*MLM*MLM];
__device__ __nv_bfloat16 g_Ztl[2][(size_t)BH*MLM*MLM];
__device__ __nv_bfloat16 g_XZh[(size_t)BH*MLM*MLM];
__device__ __nv_bfloat16 g_XZl[(size_t)BH*MLM*MLM];
__device__ __nv_bfloat16 g_WtAh[(size_t)BH*MLM*MLM];
__device__ __nv_bfloat16 g_WtAl[(size_t)BH*MLM*MLM];
__device__ __nv_bfloat16 g_WtBh[(size_t)BH*MLM*MLM];
__device__ __nv_bfloat16 g_WtBl[(size_t)BH*MLM*MLM];
__device__ float g_Zf[(size_t)BH*MLM*MLM];
__device__ float g_Opart[(size_t)NCHK*BH*MLM*DH_];
__device__ float g_dpart[(size_t)NCHK*BH*MLM];
__device__ float g_A3V[(size_t)BH*MLM*DH_];
__device__ float g_Y  [(size_t)BH*MLM*DH_];
__device__ unsigned g_maxbits[2];
__device__ unsigned g_bar_count;
__device__ unsigned g_bar_gen;

__global__ void ln_kernel(const float* __restrict__ x, const float* __restrict__ gamma,
                          const float* __restrict__ beta,
                          __nv_bfloat16* __restrict__ ohi, __nv_bfloat16* __restrict__ olo) {
    int row = blockIdx.x, tid = threadIdx.x;
    const float* xr = x + (size_t)row * D_;
    float v0 = xr[tid], v1 = xr[tid + 256];
    float s = v0 + v1, s2 = v0*v0 + v1*v1;
    #pragma unroll
    for (int o = 16; o > 0; o >>= 1) {
        s  += __shfl_xor_sync(0xffffffffu, s,  o);
        s2 += __shfl_xor_sync(0xffffffffu, s2, o);
    }
    __shared__ float sh[16];
    int w = tid >> 5;
    if ((tid & 31) == 0) { sh[w] = s; sh[w + 8] = s2; }
    __syncthreads();
    if (tid == 0) {
        float a = 0.f, b2 = 0.f;
        #pragma unroll
        for (int i = 0; i < 8; i++) { a += sh[i]; b2 += sh[i + 8]; }
        sh[0] = a; sh[8] = b2;
    }
    __syncthreads();
    float mu  = sh[0] * (1.f / D_);
    float var = sh[8] * (1.f / D_) - mu * mu;
    float inv = rsqrtf(var + 1e-5f);
    size_t base = (size_t)row * D_;
    #pragma unroll
    for (int half = 0; half < 2; half++) {
        int c = tid + half * 256;
        float v = (half == 0 ? v0 : v1);
        float nv = (v - mu) * inv * gamma[c] + beta[c];
        __nv_bfloat16 hi = __float2bfloat16(nv);
        ohi[base + c] = hi;
        olo[base + c] = __float2bfloat16(nv - __bfloat162float(hi));
    }
}

__global__ void tsplit_kernel(const float* __restrict__ W, __nv_bfloat16* __restrict__ Thi,
                              __nv_bfloat16* __restrict__ Tlo, int K, int N) {
    int idx = blockIdx.x * 256 + threadIdx.x;
    if (idx >= K * N) return;
    int k = idx / N, n = idx % N;
    float v = W[idx];
    __nv_bfloat16 hi = __float2bfloat16(v);
    Thi[(size_t)n * K + k] = hi;
    Tlo[(size_t)n * K + k] = __float2bfloat16(v - __bfloat162float(hi));
}
__global__ void vtrans_kernel(const float* __restrict__ v, __nv_bfloat16* __restrict__ vth,
                              __nv_bfloat16* __restrict__ vtl) {
    __shared__ float ts[64][68];
    int bh = blockIdx.y, k0 = blockIdx.x * 64;
    int tid = threadIdx.x;
    const float* vb = v + ((size_t)bh * NTOK + k0) * DH_;
    #pragma unroll
    for (int i = 0; i < 4; i++) {
        int lin = tid + i * 256;
        int r = lin >> 4, c4 = lin & 15;
        *(float4*)&ts[r][c4 * 4] = *(const float4*)(vb + r * 64 + c4 * 4);
    }
    __syncthreads();
    #pragma unroll
    for (int i = 0; i < 16; i++) {
        int lin = tid + i * 256;
        int dh = lin >> 6, ky = lin & 63;
        float val = ts[ky][dh];
        __nv_bfloat16 h = __float2bfloat16(val);
        size_t o = ((size_t)bh * 64 + dh) * NTOK + k0 + ky;
        vth[o] = h;
        vtl[o] = __float2bfloat16(val - __bfloat162float(h));
    }
}
__global__ void ytrans_kernel(const float* __restrict__ Y, __nv_bfloat16* __restrict__ yth,
                              __nv_bfloat16* __restrict__ ytl) {
    int bh = blockIdx.x, tid = threadIdx.x;
    #pragma unroll
    for (int i = 0; i < 64; i++) {
        int lin = tid + i * 256;
        int dh = lin >> 8, lm = lin & 255;
        float val = Y[(size_t)bh * 16384 + lm * 64 + dh];
        __nv_bfloat16 h = __float2bfloat16(val);
        size_t o = (size_t)bh * 16384 + dh * 256 + lm;
        yth[o] = h;
        ytl[o] = __float2bfloat16(val - __bfloat162float(h));
    }
}

// ---- shared GEMM tile mainloop ----
template<int NPASS>
__device__ __forceinline__ void gemm_tile_main(
        uint32_t sbase, int tid, int wid, int lane, int wm, int wn,
        const __nv_bfloat16* Ahi, const __nv_bfloat16* Alo,
        const __nv_bfloat16* Bhi, const __nv_bfloat16* Blo,
        int kdim, int m0, int n0, float (&acc)[2][8][4])
{
    const __nv_bfloat16* srcs[4] = {Ahi, Alo, Bhi, Blo};
    const int row0s[4] = {m0, m0, n0, n0};
    const int NB = (NPASS == 1) ? 2 : 4;
    int r_ld = tid >> 2, c_ld = tid & 3;
    int nch = kdim >> 5;
    #pragma unroll
    for (int bs = 0; bs < NB; bs++) {
        int bsel = (NPASS == 1) ? bs * 2 : bs;
        #pragma unroll
        for (int i = 0; i < 2; i++)
            cp_async16(sbase + (uint32_t)(bsel * 5120 + (r_ld + i * 64) * 40 + c_ld * 8) * 2,
                       srcs[bsel] + (size_t)(row0s[bsel] + r_ld + i * 64) * kdim + c_ld * 8);
    }
    CP_COMMIT();
    for (int ch = 0; ch < nch; ch++) {
        CP_WAIT0();
        __syncthreads();
        if (ch + 1 < nch) {
            int k0 = (ch + 1) << 5;
            uint32_t nxt_off = (uint32_t)((ch + 1) & 1) * 4 * 5120;
            #pragma unroll
            for (int bs = 0; bs < NB; bs++) {
                int bsel = (NPASS == 1) ? bs * 2 : bs;
                #pragma unroll
                for (int i = 0; i < 2; i++)
                    cp_async16(sbase + (uint32_t)(nxt_off + bsel * 5120 + (r_ld + i * 64) * 40 + c_ld * 8) * 2,
                               srcs[bsel] + (size_t)(row0s[bsel] + r_ld + i * 64) * kdim + k0 + c_ld * 8);
            }
            CP_COMMIT();
        }
        uint32_t stg_off = (uint32_t)(ch & 1) * 4 * 5120;
        #pragma unroll
        for (int ks = 0; ks < 32; ks += 16) {
            uint32_t Ah[2][4], Al[2][4];
            #pragma unroll
            for (int mf = 0; mf < 2; mf++) {
                int row = wm + mf * 16 + (lane & 15);
                int col = ks + ((lane >> 4) << 3);
                ldsm4(Ah[mf], sbase + (uint32_t)(stg_off + row * 40 + col) * 2);
                if (NPASS > 1) ldsm4(Al[mf], sbase + (uint32_t)(stg_off + 5120 + row * 40 + col) * 2);
            }
            #pragma unroll
            for (int p = 0; p < 4; p++) {
                int rowb = wn + (2 * p + (lane >> 4)) * 8 + (lane & 7);
                int colb = ks + ((lane >> 3) & 1) * 8;
                uint32_t Bh4[4], Bl4[4];
                ldsm4(Bh4, sbase + (uint32_t)(stg_off + 2 * 5120 + rowb * 40 + colb) * 2);
                if (NPASS > 1) ldsm4(Bl4, sbase + (uint32_t)(stg_off + 3 * 5120 + rowb * 40 + colb) * 2);
                #pragma unroll
                for (int mf = 0; mf < 2; mf++) {
                    mma_bf16p(acc[mf][2*p],   Ah[mf], Bh4[0], Bh4[1]);
                    mma_bf16p(acc[mf][2*p+1], Ah[mf], Bh4[2], Bh4[3]);
                    if (NPASS > 1) {
                        mma_bf16p(acc[mf][2*p],   Ah[mf], Bl4[0], Bl4[1]);
                        mma_bf16p(acc[mf][2*p+1], Ah[mf], Bl4[2], Bl4[3]);
                        mma_bf16p(acc[mf][2*p],   Al[mf], Bh4[0], Bh4[1]);
                        mma_bf16p(acc[mf][2*p+1], Al[mf], Bh4[2], Bh4[3]);
                    }
                }
            }
        }
    }
    __syncthreads();
}

__device__ __forceinline__ void stage_acc(char* smem, int tid, int wid, int lane, int wm, int wn,
                                          float (&acc)[2][8][4]) {
    float* stg = reinterpret_cast<float*>(smem);
    int r = lane >> 2, c = (lane & 3) * 2;
    #pragma unroll
    for (int mf = 0; mf < 2; mf++)
        #pragma unroll
        for (int nf = 0; nf < 8; nf++) {
            int rr = wm + mf * 16 + r, cc = wn + nf * 8 + c;
            *reinterpret_cast<float2*>(&stg[rr * 132 + cc]) = make_float2(acc[mf][nf][0], acc[mf][nf][1]);
            *reinterpret_cast<float2*>(&stg[(rr + 8) * 132 + cc]) = make_float2(acc[mf][nf][2], acc[mf][nf][3]);
        }
    __syncthreads();
}

// ---- standalone GEMM kernel (modes 0/1) ----
#define TCG_SMEM (2 * 4 * 5120 * 2)
template<int NPASS>
__global__ void __launch_bounds__(256, 2) tc_gemm(
        const __nv_bfloat16* __restrict__ Ahi, const __nv_bfloat16* __restrict__ Alo,
        const __nv_bfloat16* __restrict__ Bhi, const __nv_bfloat16* __restrict__ Blo,
        int K, int mode,
        float* __restrict__ qp, float* __restrict__ kp, float* __restrict__ vp,
        float* __restrict__ Cout, const float* __restrict__ bias, const float* __restrict__ addx,
        __nv_bfloat16* __restrict__ Nhi, __nv_bfloat16* __restrict__ Nlo,
        __nv_bfloat16* __restrict__ Thi, __nv_bfloat16* __restrict__ Tlo)
{
    extern __shared__ __align__(16) char smem[];
    uint32_t sbase = smem_to_u32(smem);
    int tid = threadIdx.x;
    int wid = tid >> 5, lane = tid & 31;
    int wm = (wid & 3) * 32, wn = (wid >> 2) * 64;
    int m0 = blockIdx.y * 128, n0 = blockIdx.x * 128;

    float acc[2][8][4];
    #pragma unroll
    for (int a = 0; a < 2; a++)
        #pragma unroll
        for (int b = 0; b < 8; b++)
            #pragma unroll
            for (int c = 0; c < 4; c++) acc[a][b][c] = 0.f;

    gemm_tile_main<NPASS>(sbase, tid, wid, lane, wm, wn, Ahi, Alo, Bhi, Blo, K, m0, n0, acc);
    stage_acc(smem, tid, wid, lane, wm, wn, acc);
    float* stg = reinterpret_cast<float*>(smem);

    if (mode == 0) {
        #pragma unroll 4
        for (int i = 0; i < 16; i++) {
            int lin = tid + (i << 8);
            int token = lin >> 5, c4 = lin & 31;
            int gn = n0 + (c4 << 2);
            float4 v = *reinterpret_cast<float4*>(&stg[token * 132 + (c4 << 2)]);
            int gmm = m0 + token;
            int b_ = gmm >> 13, n_ = gmm & 8191;
            int sec = gn >> 9, cc = gn & 511, h_ = cc >> 6, dh = cc & 63;
            size_t idx = ((((size_t)b_ * H_ + h_) * NTOK) + n_) * DH_ + dh;
            if (sec == 2) {
                *reinterpret_cast<float4*>(&vp[idx]) = v;
            } else {
                if (sec == 0) { v.x *= 0.125f; v.y *= 0.125f; v.z *= 0.125f; v.w *= 0.125f; }
                float* fp = (sec == 0) ? qp : kp;
                __nv_bfloat16* hp = (sec == 0) ? Nhi : Thi;
                __nv_bfloat16* lp = (sec == 0) ? Nlo : Tlo;
                *reinterpret_cast<float4*>(&fp[idx]) = v;
                float vv[4] = {v.x, v.y, v.z, v.w};
                __nv_bfloat16 hb[4], lb[4];
                #pragma unroll
                for (int t2 = 0; t2 < 4; t2++) {
                    hb[t2] = __float2bfloat16(vv[t2]);
                    lb[t2] = __float2bfloat16(vv[t2] - __bfloat162float(hb[t2]));
                }
                *reinterpret_cast<uint2*>(&hp[idx]) = *reinterpret_cast<uint2*>(hb);
                *reinterpret_cast<uint2*>(&lp[idx]) = *reinterpret_cast<uint2*>(lb);
            }
        }
    } else {
        #pragma unroll 4
        for (int i = 0; i < 16; i++) {
            int lin = tid + (i << 8);
            int token = lin >> 5, c4 = lin & 31;
            int gn = n0 + (c4 << 2);
            int gmm = m0 + token;
            float4 v = *reinterpret_cast<float4*>(&stg[token * 132 + (c4 << 2)]);
            float4 bb = *reinterpret_cast<const float4*>(&bias[gn]);
            float4 xx = *reinterpret_cast<const float4*>(&addx[(size_t)gmm * 512 + gn]);
            v.x += bb.x + xx.x; v.y += bb.y + xx.y; v.z += bb.z + xx.z; v.w += bb.w + xx.w;
            *reinterpret_cast<float4*>(&Cout[(size_t)gmm * 512 + gn]) = v;
        }
    }
}

// ---- persistent pinv ----
__device__ __forceinline__ void grid_barrier() {
    __syncthreads();
    if (threadIdx.x == 0) {
        __threadfence();
        unsigned gen = atomicAdd(&g_bar_gen, 0u);
        unsigned ticket = atomicAdd(&g_bar_count, 1u);
        if (ticket == 127u) {
            g_bar_count = 0u;
            __threadfence();
            atomicAdd(&g_bar_gen, 1u);
        } else {
            while (atomicAdd(&g_bar_gen, 0u) == gen) { }
        }
    }
    __syncthreads();
}

template<int NPASS>
__device__ __forceinline__ void pinv_stage(char* smem, uint32_t sbase,
        const __nv_bfloat16* Ahi, const __nv_bfloat16* Alo,
        const __nv_bfloat16* Bhi, const __nv_bfloat16* Blo,
        __nv_bfloat16* Nhi, __nv_bfloat16* Nlo,
        __nv_bfloat16* Thi, __nv_bfloat16* Tlo,
        float* Cf32, float alpha, float diagc, float beta,
        size_t oz, int m0, int n0)
{
    int tid = threadIdx.x;
    int wid = tid >> 5, lane = tid & 31;
    int wm = (wid & 3) * 32, wn = (wid >> 2) * 64;
    float acc[2][8][4];
    #pragma unroll
    for (int a = 0; a < 2; a++)
        #pragma unroll
        for (int b = 0; b < 8; b++)
            #pragma unroll
            for (int c = 0; c < 4; c++) acc[a][b][c] = 0.f;
    gemm_tile_main<NPASS>(sbase, tid, wid, lane, wm, wn,
        Ahi + oz, Alo + oz, Bhi + oz, Blo + oz, MLM, m0, n0, acc);
    stage_acc(smem, tid, wid, lane, wm, wn, acc);
    float* stg = reinterpret_cast<float*>(smem);
    if (Thi) {
        #pragma unroll 4
        for (int i = 0; i < 64; i++) {
            int idx = tid + (i << 8);
            int gn_l = idx >> 7, gm_l = idx & 127;
            int gmm = m0 + gm_l, gn = n0 + gn_l;
            float v = stg[gm_l * 132 + gn_l];
            float t = (gmm == gn ? diagc : 0.f) - beta * v;
            __nv_bfloat16 h = __float2bfloat16(t);
            Thi[oz + (size_t)gn * 256 + gmm] = h;
            Tlo[oz + (size_t)gn * 256 + gmm] = __float2bfloat16(t - __bfloat162float(h));
        }
    }
    if (Nhi) {
        #pragma unroll 4
        for (int i = 0; i < 16; i++) {
            int lin = tid + (i << 8);
            int token = lin >> 5, c4 = lin & 31;
            int gn = n0 + (c4 << 2);
            int gmm = m0 + token;
            float4 v = *reinterpret_cast<float4*>(&stg[token * 132 + (c4 << 2)]);
            float vv[4] = {v.x * alpha, v.y * alpha, v.z * alpha, v.w * alpha};
            __nv_bfloat16 h[4], l2[4];
            #pragma unroll
            for (int t2 = 0; t2 < 4; t2++) {
                h[t2] = __float2bfloat16(vv[t2]);
                l2[t2] = __float2bfloat16(vv[t2] - __bfloat162float(h[t2]));
            }
            *reinterpret_cast<uint2*>(&Nhi[oz + (size_t)gmm * 256 + gn]) = *reinterpret_cast<uint2*>(h);
            *reinterpret_cast<uint2*>(&Nlo[oz + (size_t)gmm * 256 + gn]) = *reinterpret_cast<uint2*>(l2);
        }
    }
    if (Cf32) {
        #pragma unroll 4
        for (int i = 0; i < 16; i++) {
            int lin = tid + (i << 8);
            int token = lin >> 5, c4 = lin & 31;
            int gn = n0 + (c4 << 2);
            int gmm = m0 + token;
            float4 v = *reinterpret_cast<float4*>(&stg[token * 132 + (c4 << 2)]);
            v.x *= alpha; v.y *= alpha; v.z *= alpha; v.w *= alpha;
            *reinterpret_cast<float4*>(&Cf32[oz + (size_t)gmm * 256 + gn]) = v;
        }
    }
    __syncthreads();
}

__global__ void __launch_bounds__(256, 2) pinv_persistent(
        const __nv_bfloat16* __restrict__ Xh, const __nv_bfloat16* __restrict__ Xl,
        __nv_bfloat16* __restrict__ Znh0, __nv_bfloat16* __restrict__ Znl0,
        __nv_bfloat16* __restrict__ Zth0, __nv_bfloat16* __restrict__ Ztl0,
        __nv_bfloat16* __restrict__ XZh, __nv_bfloat16* __restrict__ XZl,
        __nv_bfloat16* __restrict__ WtAh, __nv_bfloat16* __restrict__ WtAl,
        __nv_bfloat16* __restrict__ WtBh, __nv_bfloat16* __restrict__ WtBl,
        float* __restrict__ Zf)
{
    extern __shared__ __align__(16) char smem[];
    uint32_t sbase = smem_to_u32(smem);
    int b = blockIdx.x;
    size_t oz = (size_t)(b >> 2) * 65536;
    int m0 = ((b >> 1) & 1) * 128, n0 = (b & 1) * 128;
    const size_t SB = (size_t)BH * 65536;

    int cur = 0;
    for (int it = 0; it < 6; it++) {
        __nv_bfloat16* Znc = Znh0 + cur * SB; __nv_bfloat16* Znlc = Znl0 + cur * SB;
        __nv_bfloat16* Ztc = Zth0 + cur * SB; __nv_bfloat16* Ztlc = Ztl0 + cur * SB;
        int nxt = cur ^ 1;
        __nv_bfloat16* Znn = Znh0 + nxt * SB; __nv_bfloat16* Znln = Znl0 + nxt * SB;
        __nv_bfloat16* Ztn = Zth0 + nxt * SB; __nv_bfloat16* Ztln = Ztl0 + nxt * SB;
        if (it < 5) {
            pinv_stage<1>(smem, sbase, Xh, Xl, Ztc, Ztlc, XZh, XZl, WtAh, WtAl, nullptr, 1.f, 7.f, 1.f, oz, m0, n0);
            grid_barrier();
            pinv_stage<1>(smem, sbase, XZh, XZl, WtAh, WtAl, nullptr, nullptr, WtBh, WtBl, nullptr, 1.f, 15.f, 1.f, oz, m0, n0);
            grid_barrier();
            pinv_stage<1>(smem, sbase, XZh, XZl, WtBh, WtBl, nullptr, nullptr, WtAh, WtAl, nullptr, 1.f, 13.f, 1.f, oz, m0, n0);
            grid_barrier();
            pinv_stage<1>(smem, sbase, Znc, Znlc, WtAh, WtAl, Znn, Znln, Ztn, Ztln, nullptr, 0.25f, 0.f, -0.25f, oz, m0, n0);
            grid_barrier();
        } else {
            pinv_stage<2>(smem, sbase, Xh, Xl, Ztc, Ztlc, XZh, XZl, WtAh, WtAl, nullptr, 1.f, 7.f, 1.f, oz, m0, n0);
            grid_barrier();
            pinv_stage<2>(smem, sbase, XZh, XZl, WtAh, WtAl, nullptr, nullptr, WtBh, WtBl, nullptr, 1.f, 15.f, 1.f, oz, m0, n0);
            grid_barrier();
            pinv_stage<2>(smem, sbase, XZh, XZl, WtBh, WtBl, nullptr, nullptr, WtAh, WtAl, nullptr, 1.f, 13.f, 1.f, oz, m0, n0);
            grid_barrier();
            pinv_stage<2>(smem, sbase, Znc, Znlc, WtAh, WtAl, nullptr, nullptr, nullptr, nullptr, Zf, 0.25f, 0.f, -0.25f, oz, m0, n0);
        }
        cur = nxt;
    }
}

// SIMT SGEMM for Y = Zf @ A3V
__global__ void __launch_bounds__(256) sgemm_kernel(
        const float* __restrict__ A, const float* __restrict__ B, float* __restrict__ C,
        int M, int N, int K, size_t sA, size_t sB, size_t sC)
{
    int bz = blockIdx.z;
    A += (size_t)bz * sA; B += (size_t)bz * sB; C += (size_t)bz * sC;
    int m0 = blockIdx.y * 128, n0 = blockIdx.x * 128;
    __shared__ float As[8][128];
    __shared__ float Bs[8][128];
    int tid = threadIdx.x;
    int tx = tid & 15, ty = tid >> 4;
    float acc[8][8];
    #pragma unroll
    for (int i = 0; i < 8; i++)
        #pragma unroll
        for (int j = 0; j < 8; j++) acc[i][j] = 0.f;
    for (int k0 = 0; k0 < K; k0 += 8) {
        #pragma unroll
        for (int i = 0; i < 4; i++) {
            int lin = tid + i * 256;
            int kk = lin & 7, mm = lin >> 3;
            int gmm = m0 + mm, gk = k0 + kk;
            As[kk][mm] = (gmm < M && gk < K) ? A[(size_t)gmm * K + gk] : 0.f;
        }
        #pragma unroll
        for (int i = 0; i < 4; i++) {
            int lin = tid + i * 256;
            int nn = lin & 127, kk = lin >> 7;
            int gn = n0 + nn, gk = k0 + kk;
            Bs[kk][nn] = (gn < N && gk < K) ? B[(size_t)gk * N + gn] : 0.f;
        }
        __syncthreads();
        #pragma unroll
        for (int kk = 0; kk < 8; kk++) {
            float a[8], b[8];
            *(float4*)&a[0] = *(const float4*)&As[kk][ty * 8];
            *(float4*)&a[4] = *(const float4*)&As[kk][ty * 8 + 4];
            *(float4*)&b[0] = *(const float4*)&Bs[kk][tx * 8];
            *(float4*)&b[4] = *(const float4*)&Bs[kk][tx * 8 + 4];
            #pragma unroll
            for (int i = 0; i < 8; i++)
                #pragma unroll
                for (int j = 0; j < 8; j++) acc[i][j] += a[i] * b[j];
        }
        __syncthreads();
    }
    #pragma unroll
    for (int i = 0; i < 8; i++) {
        int gmm = m0 + ty * 8 + i;
        if (gmm >= M) continue;
        #pragma unroll
        for (int j = 0; j < 8; j++) {
            int gn = n0 + tx * 8 + j;
            if (gn >= N) continue;
            C[(size_t)gmm * N + gn] = acc[i][j];
        }
    }
}

__global__ void landmark_kernel(const float* __restrict__ q, const float* __restrict__ k,
                                float* __restrict__ ql, float* __restrict__ kl,
                                __nv_bfloat16* __restrict__ qlh, __nv_bfloat16* __restrict__ qll,
                                __nv_bfloat16* __restrict__ klh, __nv_bfloat16* __restrict__ kll) {
    int bh = blockIdx.x, m = blockIdx.y;
    int dh = threadIdx.x;
    size_t base = ((size_t)bh * NTOK + (size_t)m * LSEG) * DH_ + dh;
    float aq = 0.f, ak = 0.f;
    #pragma unroll
    for (int i = 0; i < LSEG; i++) {
        aq += q[base + (size_t)i * DH_];
        ak += k[base + (size_t)i * DH_];
    }
    size_t o = ((size_t)bh * MLM + m) * DH_ + dh;
    float qv = aq * (1.f / LSEG), kv = ak * (1.f / LSEG);
    ql[o] = qv; kl[o] = kv;
    __nv_bfloat16 qh = __float2bfloat16(qv);
    qlh[o] = qh; qll[o] = __float2bfloat16(qv - __bfloat162float(qh));
    __nv_bfloat16 kh = __float2bfloat16(kv);
    klh[o] = kh; kll[o] = __float2bfloat16(kv - __bfloat162float(kh));
}

#define ATTN2_SMEM ((256 * 68 + 32 * 64 + 8) * 4)
__global__ void attn2_kernel(const float* __restrict__ ql, const float* __restrict__ kl,
                             float* __restrict__ X,
                             __nv_bfloat16* __restrict__ Xh, __nv_bfloat16* __restrict__ Xl) {
    extern __shared__ __align__(16) float sh2[];
    float* kls  = sh2;
    float* qs   = sh2 + 256 * 68;
    float* wsum = qs + 32 * 64;
    int bh = blockIdx.x, mt = blockIdx.y;
    int tid = threadIdx.x;
    #pragma unroll
    for (int i = 0; i < 16; i++) {
        int lin = tid + i * 256;
        int r = lin >> 4, c = lin & 15;
        *(float4*)&kls[r * 68 + c * 4] = *(const float4*)&kl[((size_t)bh * MLM + r) * DH_ + c * 4];
    }
    #pragma unroll
    for (int i = 0; i < 2; i++) {
        int lin = tid + i * 256;
        int r = lin >> 4, c = lin & 15;
        *(float4*)&qs[r * 64 + c * 4] = *(const float4*)&ql[((size_t)bh * MLM + mt * 32 + r) * DH_ + c * 4];
    }
    __syncthreads();
    int j = tid, wid = tid >> 5, lane = tid & 31;
    const float* kr = &kls[j * 68];
    for (int ml = 0; ml < 32; ml++) {
        const float* qr = &qs[ml * 64];
        float a0 = 0.f, a1 = 0.f, a2 = 0.f, a3 = 0.f;
        #pragma unroll
        for (int d4 = 0; d4 < 16; d4++) {
            float4 kv = *(const float4*)&kr[d4 * 4];
            float4 qv = *(const float4*)&qr[d4 * 4];
            a0 += qv.x * kv.x; a1 += qv.y * kv.y; a2 += qv.z * kv.z; a3 += qv.w * kv.w;
        }
        float e = fexp(a0 + a1 + a2 + a3);
        float t = e;
        #pragma unroll
        for (int o = 16; o > 0; o >>= 1) t += __shfl_xor_sync(0xffffffffu, t, o);
        if (lane == 0) wsum[wid] = t;
        __syncthreads();
        float S = 0.f;
        #pragma unroll
        for (int w = 0; w < 8; w++) S += wsum[w];
        float val = e * (1.f / S);
        size_t o = ((size_t)bh * MLM + mt * 32 + ml) * MLM + j;
        X[o] = val;
        __nv_bfloat16 h = __float2bfloat16(val);
        Xh[o] = h;
        Xl[o] = __float2bfloat16(val - __bfloat162float(h));
        __syncthreads();
    }
}

__global__ void initmax_kernel(unsigned* mb) { mb[0] = 0u; mb[1] = 0u; g_bar_count = 0u; g_bar_gen = 0u; }
__global__ void rowcol_kernel(const float* __restrict__ X, unsigned* mb) {
    int bh = blockIdx.x, i = threadIdx.x;
    const float* Xm = X + (size_t)bh * MLM * MLM;
    float rs = 0.f, cs = 0.f;
    for (int j = 0; j < MLM; j++) {
        rs += fabsf(Xm[(size_t)i * MLM + j]);
        cs += fabsf(Xm[(size_t)j * MLM + i]);
    }
    #pragma unroll
    for (int o = 16; o > 0; o >>= 1) {
        rs = fmaxf(rs, __shfl_xor_sync(0xffffffffu, rs, o));
        cs = fmaxf(cs, __shfl_xor_sync(0xffffffffu, cs, o));
    }
    __shared__ float shr[8], shc[8];
    int w = i >> 5;
    if ((i & 31) == 0) { shr[w] = rs; shc[w] = cs; }
    __syncthreads();
    if (i == 0) {
        float mr = shr[0], mc = shc[0];
        #pragma unroll
        for (int k2 = 1; k2 < 8; k2++) { mr = fmaxf(mr, shr[k2]); mc = fmaxf(mc, shc[k2]); }
        atomicMax(&mb[0], __float_as_uint(mr));
        atomicMax(&mb[1], __float_as_uint(mc));
    }
}
__global__ void zinit_kernel(const float* __restrict__ X, const unsigned* __restrict__ mb,
                             __nv_bfloat16* __restrict__ Znh, __nv_bfloat16* __restrict__ Znl,
                             __nv_bfloat16* __restrict__ Zth, __nv_bfloat16* __restrict__ Ztl) {
    float inv = 1.f / (__uint_as_float(mb[0]) * __uint_as_float(mb[1]));
    size_t idx = (size_t)blockIdx.x * 256 + threadIdx.x;
    int bh = (int)(idx >> 16);
    int r = (int)((idx >> 8) & 255);
    int c = (int)(idx & 255);
    float tv = X[idx] * inv;
    __nv_bfloat16 th = __float2bfloat16(tv);
    Zth[idx] = th; Ztl[idx] = __float2bfloat16(tv - __bfloat162float(th));
    float nv = X[((size_t)bh << 16) + ((size_t)c << 8) + r] * inv;
    __nv_bfloat16 nh = __float2bfloat16(nv);
    Znh[idx] = nh; Znl[idx] = __float2bfloat16(nv - __bfloat162float(nh));
}

// attn3@v via MMA, cp.async double-buffered k/v tiles.
// smem elem offsets: qh 0 [256][72]; ql 18432; stage s at 36864 + s*9728:
//   kh +0 [32][72], kl +2304, vh +4608 [64][40], vl +7168.
#define A3_SMEM ((36864 + 2 * 9728) * 2)
__global__ void __launch_bounds__(256, 1) attn3v_mma(
        const __nv_bfloat16* __restrict__ qlh_, const __nv_bfloat16* __restrict__ qll_,
        const __nv_bfloat16* __restrict__ kh_, const __nv_bfloat16* __restrict__ klo_,
        const __nv_bfloat16* __restrict__ vth_, const __nv_bfloat16* __restrict__ vtl_,
        float* __restrict__ Opart, float* __restrict__ denpart)
{
    extern __shared__ __align__(16) __nv_bfloat16 sm3[];
    uint32_t sb = smem_to_u32(sm3);
    int tid = threadIdx.x, wid = tid >> 5, lane = tid & 31;
    int chunk = blockIdx.x, bh = blockIdx.y;
    int key0 = chunk * (NTOK / NCHK);
    {
        size_t qb = (size_t)bh * MLM * DH_;
        #pragma unroll
        for (int i = 0; i < 8; i++) {
            int lin = tid + i * 256;
            int r = lin >> 3, c = lin & 7;
            *(uint4*)(sm3 + r * 72 + c * 8) = *(const uint4*)(qlh_ + qb + r * 64 + c * 8);
            *(uint4*)(sm3 + 18432 + r * 72 + c * 8) = *(const uint4*)(qll_ + qb + r * 64 + c * 8);
        }
    }
    __syncthreads();
    uint32_t Ah[2][4][4], Al[2][4][4];
    #pragma unroll
    for (int mf = 0; mf < 2; mf++) {
        int row = wid * 32 + mf * 16 + (lane & 15);
        #pragma unroll
        for (int ks = 0; ks < 4; ks++) {
            int col = ks * 16 + ((lane >> 4) << 3);
            ldsm4(Ah[mf][ks], sb + (uint32_t)(row * 72 + col) * 2);
            ldsm4(Al[mf][ks], sb + (uint32_t)(18432 + row * 72 + col) * 2);
        }
    }
    float Oacc[2][8][4];
    #pragma unroll
    for (int a = 0; a < 2; a++)
        #pragma unroll
        for (int b = 0; b < 8; b++)
            #pragma unroll
            for (int c = 0; c < 4; c++) Oacc[a][b][c] = 0.f;
    float den[2][2] = {{0.f, 0.f}, {0.f, 0.f}};

    int r_k = tid >> 3, c_k = tid & 7;      // k: 32 rows x 8 col-groups
    int r_v = tid >> 2, c_v = tid & 3;      // v: 64 rows x 4 col-groups
    const int NIT = (NTOK / NCHK) / 32;     // 32

    // issue stage 0
    {
        int kt0 = key0;
        uint32_t s0 = 36864;
        cp_async16(sb + (uint32_t)(s0 + r_k * 72 + c_k * 8) * 2,
                   kh_ + ((size_t)bh * NTOK + kt0 + r_k) * 64 + c_k * 8);
        cp_async16(sb + (uint32_t)(s0 + 2304 + r_k * 72 + c_k * 8) * 2,
                   klo_ + ((size_t)bh * NTOK + kt0 + r_k) * 64 + c_k * 8);
        cp_async16(sb + (uint32_t)(s0 + 4608 + r_v * 40 + c_v * 8) * 2,
                   vth_ + ((size_t)bh * 64 + r_v) * NTOK + kt0 + c_v * 8);
        cp_async16(sb + (uint32_t)(s0 + 7168 + r_v * 40 + c_v * 8) * 2,
                   vtl_ + ((size_t)bh * 64 + r_v) * NTOK + kt0 + c_v * 8);
    }
    CP_COMMIT();

    for (int t32 = 0; t32 < NIT; t32++) {
        CP_WAIT0();
        __syncthreads();
        if (t32 + 1 < NIT) {
            int kt1 = key0 + (t32 + 1) * 32;
            uint32_t sn = 36864 + (uint32_t)((t32 + 1) & 1) * 9728;
            cp_async16(sb + (uint32_t)(sn + r_k * 72 + c_k * 8) * 2,
                       kh_ + ((size_t)bh * NTOK + kt1 + r_k) * 64 + c_k * 8);
            cp_async16(sb + (uint32_t)(sn + 2304 + r_k * 72 + c_k * 8) * 2,
                       klo_ + ((size_t)bh * NTOK + kt1 + r_k) * 64 + c_k * 8);
            cp_async16(sb + (uint32_t)(sn + 4608 + r_v * 40 + c_v * 8) * 2,
                       vth_ + ((size_t)bh * 64 + r_v) * NTOK + kt1 + c_v * 8);
            cp_async16(sb + (uint32_t)(sn + 7168 + r_v * 40 + c_v * 8) * 2,
                       vtl_ + ((size_t)bh * 64 + r_v) * NTOK + kt1 + c_v * 8);
            CP_COMMIT();
        }
        uint32_t kb = 36864 + (uint32_t)(t32 & 1) * 9728;
        uint32_t klb = kb + 2304, vhb = kb + 4608, vlb = kb + 7168;
        float S[2][4][4];
        #pragma unroll
        for (int a = 0; a < 2; a++)
            #pragma unroll
            for (int b = 0; b < 4; b++)
                #pragma unroll
                for (int c = 0; c < 4; c++) S[a][b][c] = 0.f;
        #pragma unroll
        for (int ks = 0; ks < 4; ks++) {
            #pragma unroll
            for (int np = 0; np < 2; np++) {
                int row = np * 16 + ((lane >> 4) & 1) * 8 + (lane & 7);
                int col = ks * 16 + ((lane >> 3) & 1) * 8;
                uint32_t bh4[4], bl4[4];
                ldsm4(bh4, sb + (uint32_t)(kb + row * 72 + col) * 2);
                ldsm4(bl4, sb + (uint32_t)(klb + row * 72 + col) * 2);
                #pragma unroll
                for (int mf = 0; mf < 2; mf++) {
                    mma_bf16p(S[mf][2*np],   Ah[mf][ks], bh4[0], bh4[1]);
                    mma_bf16p(S[mf][2*np],   Ah[mf][ks], bl4[0], bl4[1]);
                    mma_bf16p(S[mf][2*np],   Al[mf][ks], bh4[0], bh4[1]);
                    mma_bf16p(S[mf][2*np+1], Ah[mf][ks], bh4[2], bh4[3]);
                    mma_bf16p(S[mf][2*np+1], Ah[mf][ks], bl4[2], bl4[3]);
                    mma_bf16p(S[mf][2*np+1], Al[mf][ks], bh4[2], bh4[3]);
                }
            }
        }
        #pragma unroll
        for (int kt = 0; kt < 2; kt++) {
            uint32_t pah[2][4], pal[2][4];
            #pragma unroll
            for (int mf = 0; mf < 2; mf++) {
                float e[8];
                #pragma unroll
                for (int j = 0; j < 4; j++) { e[j] = fexp(S[mf][2*kt][j]); e[4+j] = fexp(S[mf][2*kt+1][j]); }
                den[mf][0] += e[0] + e[1] + e[4] + e[5];
                den[mf][1] += e[2] + e[3] + e[6] + e[7];
                #pragma unroll
                for (int j = 0; j < 4; j++) {
                    __nv_bfloat162 h2 = __floats2bfloat162_rn(e[2*j], e[2*j+1]);
                    pah[mf][j] = *(uint32_t*)&h2;
                    float r0 = e[2*j]   - __bfloat162float(__low2bfloat16(h2));
                    float r1 = e[2*j+1] - __bfloat162float(__high2bfloat16(h2));
                    __nv_bfloat162 l2 = __floats2bfloat162_rn(r0, r1);
                    pal[mf][j] = *(uint32_t*)&l2;
                }
            }
            #pragma unroll
            for (int np = 0; np < 4; np++) {
                int row = np * 16 + ((lane >> 4) & 1) * 8 + (lane & 7);
                int col = kt * 16 + ((lane >> 3) & 1) * 8;
                uint32_t vh4[4], vl4[4];
                ldsm4(vh4, sb + (uint32_t)(vhb + row * 40 + col) * 2);
                ldsm4(vl4, sb + (uint32_t)(vlb + row * 40 + col) * 2);
                #pragma unroll
                for (int mf = 0; mf < 2; mf++) {
                    mma_bf16p(Oacc[mf][2*np],   pah[mf], vh4[0], vh4[1]);
                    mma_bf16p(Oacc[mf][2*np],   pah[mf], vl4[0], vl4[1]);
                    mma_bf16p(Oacc[mf][2*np],   pal[mf], vh4[0], vh4[1]);
                    mma_bf16p(Oacc[mf][2*np+1], pah[mf], vh4[2], vh4[3]);
                    mma_bf16p(Oacc[mf][2*np+1], pah[mf], vl4[2], vl4[3]);
                    mma_bf16p(Oacc[mf][2*np+1], pal[mf], vh4[2], vh4[3]);
                }
            }
        }
    }
    #pragma unroll
    for (int mf = 0; mf < 2; mf++)
        #pragma unroll
        for (int j = 0; j < 2; j++) {
            den[mf][j] += __shfl_xor_sync(0xffffffffu, den[mf][j], 1);
            den[mf][j] += __shfl_xor_sync(0xffffffffu, den[mf][j], 2);
        }
    int g = lane >> 2, t = lane & 3;
    size_t ob = ((size_t)chunk * BH + bh) * MLM * 64;
    #pragma unroll
    for (int mf = 0; mf < 2; mf++) {
        int lm0 = wid * 32 + mf * 16 + g;
        #pragma unroll
        for (int nf = 0; nf < 8; nf++) {
            int c = nf * 8 + t * 2;
            *(float2*)&Opart[ob + (size_t)lm0 * 64 + c] = make_float2(Oacc[mf][nf][0], Oacc[mf][nf][1]);
            *(float2*)&Opart[ob + (size_t)(lm0 + 8) * 64 + c] = make_float2(Oacc[mf][nf][2], Oacc[mf][nf][3]);
        }
        if (t == 0) {
            denpart[((size_t)chunk * BH + bh) * MLM + lm0] = den[mf][0];
            denpart[((size_t)chunk * BH + bh) * MLM + lm0 + 8] = den[mf][1];
        }
    }
}

__global__ void a3v_reduce(const float* __restrict__ Opart, const float* __restrict__ denpart,
                           float* __restrict__ A3V) {
    int idx = blockIdx.x * 256 + threadIdx.x;
    int bh = idx >> 14, lm = (idx >> 6) & 255;
    float s = 0.f, d = 0.f;
    #pragma unroll
    for (int c = 0; c < NCHK; c++) {
        s += Opart[((size_t)c * BH + bh) * 16384 + (idx & 16383)];
        d += denpart[((size_t)c * BH + bh) * 256 + lm];
    }
    A3V[idx] = s / d;
}

// attn1 + conv + osplit fused
#define A1V_OFF  89088
#define A1KW_OFF (178176 + 43520)
#define A1_SMEM  (178176 + 43520 + 256)
__global__ void __launch_bounds__(256, 1) attn1_mma(
        const __nv_bfloat16* __restrict__ qh_, const __nv_bfloat16* __restrict__ qlo_,
        const __nv_bfloat16* __restrict__ klh_, const __nv_bfloat16* __restrict__ kll_,
        const __nv_bfloat16* __restrict__ yth_, const __nv_bfloat16* __restrict__ ytl_,
        const float* __restrict__ v_, const float* __restrict__ ker,
        __nv_bfloat16* __restrict__ Ohi, __nv_bfloat16* __restrict__ Olo)
{
    extern __shared__ __align__(16) __nv_bfloat16 sm1[];
    uint32_t sb = smem_to_u32(sm1);
    float* vs = reinterpret_cast<float*>(sm1 + A1V_OFF);
    float* kw = reinterpret_cast<float*>((char*)sm1 + A1KW_OFF);
    int tid = threadIdx.x, wid = tid >> 5, lane = tid & 31;
    int bh = blockIdx.y;
    int b = bh >> 3, h = bh & 7;
    {
        size_t kb = (size_t)bh * MLM * DH_;
        #pragma unroll
        for (int i = 0; i < 8; i++) {
            int lin = tid + i * 256;
            int r = lin >> 3, c = lin & 7;
            *(uint4*)(sm1 + 18432 + r * 72 + c * 8) = *(const uint4*)(klh_ + kb + r * 64 + c * 8);
            *(uint4*)(sm1 + 36864 + r * 72 + c * 8) = *(const uint4*)(kll_ + kb + r * 64 + c * 8);
        }
        size_t yb = (size_t)bh * 64 * MLM;
        #pragma unroll
        for (int i = 0; i < 8; i++) {
            int lin = tid + i * 256;
            int r = lin >> 5, c = lin & 31;
            *(uint4*)(sm1 + 55296 + r * 264 + c * 8) = *(const uint4*)(yth_ + yb + r * 256 + c * 8);
            *(uint4*)(sm1 + 72192 + r * 264 + c * 8) = *(const uint4*)(ytl_ + yb + r * 256 + c * 8);
        }
        if (tid < KER_) kw[tid] = ker[h * KER_ + tid];
    }
    const float* vb = v_ + ((size_t)b * H_ + h) * NTOK * DH_;

    for (int tt = 0; tt < A1_TPB; tt++) {
        int tile0 = (blockIdx.x * A1_TPB + tt) * 128;
        __syncthreads();
        {
            size_t qb = ((size_t)bh * NTOK + tile0) * DH_;
            #pragma unroll
            for (int i = 0; i < 4; i++) {
                int lin = tid + i * 256;
                int r = lin >> 3, c = lin & 7;
                *(uint4*)(sm1 + r * 72 + c * 8) = *(const uint4*)(qh_ + qb + r * 64 + c * 8);
                *(uint4*)(sm1 + 9216 + r * 72 + c * 8) = *(const uint4*)(qlo_ + qb + r * 64 + c * 8);
            }
            #pragma unroll
            for (int i = 0; i < 10; i++) {
                int f4 = tid + i * 256;
                int row = f4 >> 4, c4 = f4 & 15;
                int n = tile0 - 16 + row;
                float4 val = make_float4(0.f, 0.f, 0.f, 0.f);
                if (n >= 0 && n < NTOK) val = ((const float4*)(vb + (size_t)n * DH_))[c4];
                *(float4*)&vs[row * 68 + c4 * 4] = val;
            }
        }
        __syncthreads();
        uint32_t Ah[4][4], Al[4][4];
        {
            int row = wid * 16 + (lane & 15);
            #pragma unroll
            for (int ks = 0; ks < 4; ks++) {
                int col = ks * 16 + ((lane >> 4) << 3);
                ldsm4(Ah[ks], sb + (uint32_t)(row * 72 + col) * 2);
                ldsm4(Al[ks], sb + (uint32_t)(9216 + row * 72 + col) * 2);
            }
        }
        float Oacc[8][4];
        #pragma unroll
        for (int bb = 0; bb < 8; bb++)
            #pragma unroll
            for (int c = 0; c < 4; c++) Oacc[bb][c] = 0.f;
        float dlo = 0.f, dhi = 0.f;

        #pragma unroll
        for (int half = 0; half < 2; half++) {
            int lmb = half * 128;
            float S[16][4];
            #pragma unroll
            for (int bb = 0; bb < 16; bb++)
                #pragma unroll
                for (int c = 0; c < 4; c++) S[bb][c] = 0.f;
            #pragma unroll
            for (int ks = 0; ks < 4; ks++) {
                #pragma unroll
                for (int np = 0; np < 8; np++) {
                    int row = lmb + np * 16 + ((lane >> 4) & 1) * 8 + (lane & 7);
                    int col = ks * 16 + ((lane >> 3) & 1) * 8;
                    uint32_t bh4[4], bl4[4];
                    ldsm4(bh4, sb + (uint32_t)(18432 + row * 72 + col) * 2);
                    ldsm4(bl4, sb + (uint32_t)(36864 + row * 72 + col) * 2);
                    mma_bf16p(S[2*np],   Ah[ks], bh4[0], bh4[1]);
                    mma_bf16p(S[2*np],   Ah[ks], bl4[0], bl4[1]);
                    mma_bf16p(S[2*np],   Al[ks], bh4[0], bh4[1]);
                    mma_bf16p(S[2*np+1], Ah[ks], bh4[2], bh4[3]);
                    mma_bf16p(S[2*np+1], Ah[ks], bl4[2], bl4[3]);
                    mma_bf16p(S[2*np+1], Al[ks], bh4[2], bh4[3]);
                }
            }
            #pragma unroll
            for (int kt = 0; kt < 8; kt++) {
                float e[8];
                #pragma unroll
                for (int j = 0; j < 4; j++) { e[j] = fexp(S[2*kt][j]); e[4+j] = fexp(S[2*kt+1][j]); }
                dlo += e[0] + e[1] + e[4] + e[5];
                dhi += e[2] + e[3] + e[6] + e[7];
                uint32_t pah[4], pal[4];
                #pragma unroll
                for (int j = 0; j < 4; j++) {
                    __nv_bfloat162 h2 = __floats2bfloat162_rn(e[2*j], e[2*j+1]);
                    pah[j] = *(uint32_t*)&h2;
                    float r0 = e[2*j]   - __bfloat162float(__low2bfloat16(h2));
                    float r1 = e[2*j+1] - __bfloat162float(__high2bfloat16(h2));
                    __nv_bfloat162 l2 = __floats2bfloat162_rn(r0, r1);
                    pal[j] = *(uint32_t*)&l2;
                }
                #pragma unroll
                for (int np = 0; np < 4; np++) {
                    int row = np * 16 + ((lane >> 4) & 1) * 8 + (lane & 7);
                    int col = lmb + kt * 16 + ((lane >> 3) & 1) * 8;
                    uint32_t yh4[4], yl4[4];
                    ldsm4(yh4, sb + (uint32_t)(55296 + row * 264 + col) * 2);
                    ldsm4(yl4, sb + (uint32_t)(72192 + row * 264 + col) * 2);
                    mma_bf16p(Oacc[2*np],   pah, yh4[0], yh4[1]);
                    mma_bf16p(Oacc[2*np],   pah, yl4[0], yl4[1]);
                    mma_bf16p(Oacc[2*np],   pal, yh4[0], yh4[1]);
                    mma_bf16p(Oacc[2*np+1], pah, yh4[2], yh4[3]);
                    mma_bf16p(Oacc[2*np+1], pah, yl4[2], yl4[3]);
                    mma_bf16p(Oacc[2*np+1], pal, yh4[2], yh4[3]);
                }
            }
        }
        dlo += __shfl_xor_sync(0xffffffffu, dlo, 1);
        dlo += __shfl_xor_sync(0xffffffffu, dlo, 2);
        dhi += __shfl_xor_sync(0xffffffffu, dhi, 1);
        dhi += __shfl_xor_sync(0xffffffffu, dhi, 2);
        float ilo = 1.f / dlo, ihi = 1.f / dhi;
        int g = lane >> 2, t = lane & 3;
        int tok0 = tile0 + wid * 16 + g;
        int r0 = wid * 16 + g;
        size_t ob = ((size_t)b * NTOK + tok0) * D_ + h * DH_;
        #pragma unroll
        for (int nf = 0; nf < 8; nf++) {
            int c = nf * 8 + t * 2;
            float cv00 = 0.f, cv01 = 0.f, cv10 = 0.f, cv11 = 0.f;
            #pragma unroll
            for (int tap = 0; tap < KER_; tap++) {
                float w = kw[tap];
                cv00 += w * vs[(r0 + tap) * 68 + c];
                cv01 += w * vs[(r0 + tap) * 68 + c + 1];
                cv10 += w * vs[(r0 + 8 + tap) * 68 + c];
                cv11 += w * vs[(r0 + 8 + tap) * 68 + c + 1];
            }
            float o00 = Oacc[nf][0] * ilo + cv00;
            float o01 = Oacc[nf][1] * ilo + cv01;
            float o10 = Oacc[nf][2] * ihi + cv10;
            float o11 = Oacc[nf][3] * ihi + cv11;
            __nv_bfloat162 h0 = __floats2bfloat162_rn(o00, o01);
            __nv_bfloat162 l0 = __floats2bfloat162_rn(o00 - __bfloat162float(__low2bfloat16(h0)),
                                                      o01 - __bfloat162float(__high2bfloat16(h0)));
            *(uint32_t*)&Ohi[ob + c] = *(uint32_t*)&h0;
            *(uint32_t*)&Olo[ob + c] = *(uint32_t*)&l0;
            __nv_bfloat162 h1 = __floats2bfloat162_rn(o10, o11);
            __nv_bfloat162 l1 = __floats2bfloat162_rn(o10 - __bfloat162float(__low2bfloat16(h1)),
                                                      o11 - __bfloat162float(__high2bfloat16(h1)));
            *(uint32_t*)&Ohi[ob + (size_t)8 * D_ + c] = *(uint32_t*)&h1;
            *(uint32_t*)&Olo[ob + (size_t)8 * D_ + c] = *(uint32_t*)&l1;
        }
    }
}

extern "C" void kernel_launch(void* const* d_in, const int* in_sizes, int n_in,
                              void* d_out, int out_size) {
    const float* x      = (const float*)d_in[0];
    const float* gamma  = (const float*)d_in[1];
    const float* beta   = (const float*)d_in[2];
    const float* w_qkv  = (const float*)d_in[3];
    const float* res_k  = (const float*)d_in[4];
    const float* w_out  = (const float*)d_in[5];
    const float* b_out  = (const float*)d_in[6];
    float* out = (float*)d_out;

    __nv_bfloat16 *nh, *nl, *wqh, *wql, *woh, *wol, *Oh, *Ol, *Xh, *Xl;
    __nv_bfloat16 *Znh, *Znl, *Zth, *Ztl, *XZh, *XZl, *WtAh, *WtAl, *WtBh, *WtBl;
    __nv_bfloat16 *qbh, *qbl, *kbh, *kbl, *vth, *vtl, *qlh, *qll, *klh, *kll, *yth, *ytl;
    float *q, *k, *v, *ql, *kl, *X, *Zf, *A3V, *Y, *Opart, *dpart;
    unsigned* mb;
    cudaGetSymbolAddress((void**)&nh, g_nh);
    cudaGetSymbolAddress((void**)&nl, g_nl);
    cudaGetSymbolAddress((void**)&wqh, g_wqh);
    cudaGetSymbolAddress((void**)&wql, g_wql);
    cudaGetSymbolAddress((void**)&woh, g_woh);
    cudaGetSymbolAddress((void**)&wol, g_wol);
    cudaGetSymbolAddress((void**)&Oh, g_Oh);
    cudaGetSymbolAddress((void**)&Ol, g_Ol);
    cudaGetSymbolAddress((void**)&Xh, g_Xh);
    cudaGetSymbolAddress((void**)&Xl, g_Xl);
    cudaGetSymbolAddress((void**)&Znh, g_Znh);
    cudaGetSymbolAddress((void**)&Znl, g_Znl);
    cudaGetSymbolAddress((void**)&Zth, g_Zth);
    cudaGetSymbolAddress((void**)&Ztl, g_Ztl);
    cudaGetSymbolAddress((void**)&XZh, g_XZh);
    cudaGetSymbolAddress((void**)&XZl, g_XZl);
    cudaGetSymbolAddress((void**)&WtAh, g_WtAh);
    cudaGetSymbolAddress((void**)&WtAl, g_WtAl);
    cudaGetSymbolAddress((void**)&WtBh, g_WtBh);
    cudaGetSymbolAddress((void**)&WtBl, g_WtBl);
    cudaGetSymbolAddress((void**)&q,  g_q);
    cudaGetSymbolAddress((void**)&k,  g_k);
    cudaGetSymbolAddress((void**)&v,  g_v);
    cudaGetSymbolAddress((void**)&qbh, g_qbh);
    cudaGetSymbolAddress((void**)&qbl, g_qbl);
    cudaGetSymbolAddress((void**)&kbh, g_kbh);
    cudaGetSymbolAddress((void**)&kbl, g_kbl);
    cudaGetSymbolAddress((void**)&vth, g_vth);
    cudaGetSymbolAddress((void**)&vtl, g_vtl);
    cudaGetSymbolAddress((void**)&ql, g_ql);
    cudaGetSymbolAddress((void**)&kl, g_kl);
    cudaGetSymbolAddress((void**)&qlh, g_qlh);
    cudaGetSymbolAddress((void**)&qll, g_qll);
    cudaGetSymbolAddress((void**)&klh, g_klh);
    cudaGetSymbolAddress((void**)&kll, g_kll);
    cudaGetSymbolAddress((void**)&yth, g_yth);
    cudaGetSymbolAddress((void**)&ytl, g_ytl);
    cudaGetSymbolAddress((void**)&X,  g_X);
    cudaGetSymbolAddress((void**)&Zf, g_Zf);
    cudaGetSymbolAddress((void**)&Opart, g_Opart);
    cudaGetSymbolAddress((void**)&dpart, g_dpart);
    cudaGetSymbolAddress((void**)&A3V, g_A3V);
    cudaGetSymbolAddress((void**)&Y,  g_Y);
    cudaGetSymbolAddress((void**)&mb, g_maxbits);

    cudaFuncSetAttribute(attn2_kernel, cudaFuncAttributeMaxDynamicSharedMemorySize, ATTN2_SMEM);
    cudaFuncSetAttribute(tc_gemm<2>, cudaFuncAttributeMaxDynamicSharedMemorySize, TCG_SMEM);
    cudaFuncSetAttribute(pinv_persistent, cudaFuncAttributeMaxDynamicSharedMemorySize, TCG_SMEM);
    cudaFuncSetAttribute(attn3v_mma, cudaFuncAttributeMaxDynamicSharedMemorySize, A3_SMEM);
    cudaFuncSetAttribute(attn1_mma, cudaFuncAttributeMaxDynamicSharedMemorySize, A1_SMEM);

    ln_kernel<<<B_ * NTOK, 256>>>(x, gamma, beta, nh, nl);
    tsplit_kernel<<<(D_ * 3 * D_ + 255) / 256, 256>>>(w_qkv, wqh, wql, D_, 3 * D_);
    tsplit_kernel<<<(D_ * D_ + 255) / 256, 256>>>(w_out, woh, wol, D_, D_);

    tc_gemm<2><<<dim3(12, 256, 1), 256, TCG_SMEM>>>(nh, nl, wqh, wql, D_, 0,
        q, k, v, nullptr, nullptr, nullptr, qbh, qbl, kbh, kbl);

    vtrans_kernel<<<dim3(NTOK / 64, BH), 256>>>(v, vth, vtl);
    landmark_kernel<<<dim3(BH, MLM), 64>>>(q, k, ql, kl, qlh, qll, klh, kll);

    attn2_kernel<<<dim3(BH, 8), 256, ATTN2_SMEM>>>(ql, kl, X, Xh, Xl);
    initmax_kernel<<<1, 1>>>(mb);
    rowcol_kernel<<<BH, 256>>>(X, mb);
    zinit_kernel<<<8192, 256>>>(X, mb, Znh, Znl, Zth, Ztl);

    pinv_persistent<<<128, 256, TCG_SMEM>>>(Xh, Xl, Znh, Znl, Zth, Ztl,
        XZh, XZl, WtAh, WtAl, WtBh, WtBl, Zf);

    attn3v_mma<<<dim3(NCHK, BH), 256, A3_SMEM>>>(qlh, qll, kbh, kbl, vth, vtl, Opart, dpart);
    a3v_reduce<<<2048, 256>>>(Opart, dpart, A3V);

    sgemm_kernel<<<dim3(1, 2, BH), 256>>>(Zf, A3V, Y, MLM, DH_, MLM,
        (size_t)MLM * MLM, (size_t)MLM * DH_, (size_t)MLM * DH_);
    ytrans_kernel<<<BH, 256>>>(Y, yth, ytl);

    attn1_mma<<<dim3(NTOK / 128 / A1_TPB, BH), 256, A1_SMEM>>>(
        qbh, qbl, klh, kll, yth, ytl, v, res_k, Oh, Ol);

    tc_gemm<2><<<dim3(4, 256, 1), 256, TCG_SMEM>>>(Oh, Ol, woh, wol, D_, 1,
        nullptr, nullptr, nullptr, out, b_out, x, nullptr, nullptr, nullptr, nullptr);
}

// round 16
// speedup vs baseline: 6.5073x; 1.0088x over previous
#include <cuda_runtime.h>
#include <cuda_bf16.h>
#include <math.h>
#include <stdint.h>

#define B_    4
#define NTOK  8192
#define D_    512
#define H_    8
#define DH_   64
#define MLM   256
#define LSEG  32
#define BH    (B_*H_)
#define KER_  33
#define NCHK  8
#define A1_TPB 4

__device__ __forceinline__ uint32_t smem_to_u32(const void* p) {
    uint32_t a;
    asm("{ .reg .u64 t; cvta.to.shared.u64 t, %1; cvt.u32.u64 %0, t; }" : "=r"(a) : "l"(p));
    return a;
}
__device__ __forceinline__ void cp_async16(uint32_t saddr, const void* gptr) {
    asm volatile("cp.async.cg.shared.global [%0], [%1], 16;" :: "r"(saddr), "l"(gptr));
}
#define CP_COMMIT() asm volatile("cp.async.commit_group;" ::: "memory")
#define CP_WAIT0()  asm volatile("cp.async.wait_group 0;" ::: "memory")
#define CP_WAIT1()  asm volatile("cp.async.wait_group 1;" ::: "memory")
__device__ __forceinline__ void mma_bf16p(float (&d)[4], const uint32_t (&a)[4], uint32_t b0, uint32_t b1) {
    asm volatile("mma.sync.aligned.m16n8k16.row.col.f32.bf16.bf16.f32 "
        "{%0,%1,%2,%3}, {%4,%5,%6,%7}, {%8,%9}, {%0,%1,%2,%3};"
        : "+f"(d[0]), "+f"(d[1]), "+f"(d[2]), "+f"(d[3])
        : "r"(a[0]), "r"(a[1]), "r"(a[2]), "r"(a[3]), "r"(b0), "r"(b1));
}
__device__ __forceinline__ void ldsm4(uint32_t (&r)[4], uint32_t a) {
    asm volatile("ldmatrix.sync.aligned.m8n8.x4.shared.b16 {%0,%1,%2,%3}, [%4];"
        : "=r"(r[0]), "=r"(r[1]), "=r"(r[2]), "=r"(r[3]) : "r"(a));
}
__device__ __forceinline__ float fexp(float s) {
    float t = s * 1.44269504088896341f;
    float i = rintf(t);
    float f = t - i;
    float p = 1.54035303933816e-4f;
    p = p * f + 1.33335581464284e-3f;
    p = p * f + 9.61812910762848e-3f;
    p = p * f + 5.55041086648216e-2f;
    p = p * f + 2.40226506959101e-1f;
    p = p * f + 6.93147180559945e-1f;
    p = p * f + 1.0f;
    return p * __int_as_float(((int)i + 127) << 23);
}

// scratch
__device__ __nv_bfloat16 g_nh[(size_t)B_*NTOK*D_];
__device__ __nv_bfloat16 g_nl[(size_t)B_*NTOK*D_];
__device__ __nv_bfloat16 g_wqh[(size_t)3*D_*D_];
__device__ __nv_bfloat16 g_wql[(size_t)3*D_*D_];
__device__ __nv_bfloat16 g_woh[(size_t)D_*D_];
__device__ __nv_bfloat16 g_wol[(size_t)D_*D_];
__device__ __nv_bfloat16 g_Oh[(size_t)B_*NTOK*D_];
__device__ __nv_bfloat16 g_Ol[(size_t)B_*NTOK*D_];
__device__ float g_q [(size_t)BH*NTOK*DH_];
__device__ float g_k [(size_t)BH*NTOK*DH_];
__device__ float g_v [(size_t)BH*NTOK*DH_];
__device__ __nv_bfloat16 g_qbh[(size_t)BH*NTOK*DH_];
__device__ __nv_bfloat16 g_qbl[(size_t)BH*NTOK*DH_];
__device__ __nv_bfloat16 g_kbh[(size_t)BH*NTOK*DH_];
__device__ __nv_bfloat16 g_kbl[(size_t)BH*NTOK*DH_];
__device__ __nv_bfloat16 g_vth[(size_t)BH*NTOK*DH_];
__device__ __nv_bfloat16 g_vtl[(size_t)BH*NTOK*DH_];
__device__ float g_ql[(size_t)BH*MLM*DH_];
__device__ float g_kl[(size_t)BH*MLM*DH_];
__device__ __nv_bfloat16 g_qlh[(size_t)BH*MLM*DH_];
__device__ __nv_bfloat16 g_qll[(size_t)BH*MLM*DH_];
__device__ __nv_bfloat16 g_klh[(size_t)BH*MLM*DH_];
__device__ __nv_bfloat16 g_kll[(size_t)BH*MLM*DH_];
__device__ __nv_bfloat16 g_yth[(size_t)BH*MLM*DH_];
__device__ __nv_bfloat16 g_ytl[(size_t)BH*MLM*DH_];
__device__ float g_X [(size_t)BH*MLM*MLM];
__device__ __nv_bfloat16 g_Xh[(size_t)BH*MLM*MLM];
__device__ __nv_bfloat16 g_Xl[(size_t)BH*MLM*MLM];
__device__ __nv_bfloat16 g_Znh[2][(size_t)BH*MLM*MLM];
__device__ __nv_bfloat16 g_Znl[2][(size_t)BH*MLM*MLM];
__device__ __nv_bfloat16 g_Zth[2][(size_t)BH*MLM*MLM];
__device__ __nv_bfloat16 g_Ztl[2][(size_t)BH*MLM*MLM];
__device__ __nv_bfloat16 g_XZh[(size_t)BH*MLM*MLM];
__device__ __nv_bfloat16 g_XZl[(size_t)BH*MLM*MLM];
__device__ __nv_bfloat16 g_WtAh[(size_t)BH*MLM*MLM];
__device__ __nv_bfloat16 g_WtAl[(size_t)BH*MLM*MLM];
__device__ __nv_bfloat16 g_WtBh[(size_t)BH*MLM*MLM];
__device__ __nv_bfloat16 g_WtBl[(size_t)BH*MLM*MLM];
__device__ float g_Zf[(size_t)BH*MLM*MLM];
__device__ float g_Opart[(size_t)NCHK*BH*MLM*DH_];
__device__ float g_dpart[(size_t)NCHK*BH*MLM];
__device__ float g_A3V[(size_t)BH*MLM*DH_];
__device__ float g_Y  [(size_t)BH*MLM*DH_];
__device__ unsigned g_maxbits[2];
__device__ unsigned g_bar_count;
__device__ unsigned g_bar_gen;

__global__ void ln_kernel(const float* __restrict__ x, const float* __restrict__ gamma,
                          const float* __restrict__ beta,
                          __nv_bfloat16* __restrict__ ohi, __nv_bfloat16* __restrict__ olo) {
    int row = blockIdx.x, tid = threadIdx.x;
    const float* xr = x + (size_t)row * D_;
    float v0 = xr[tid], v1 = xr[tid + 256];
    float s = v0 + v1, s2 = v0*v0 + v1*v1;
    #pragma unroll
    for (int o = 16; o > 0; o >>= 1) {
        s  += __shfl_xor_sync(0xffffffffu, s,  o);
        s2 += __shfl_xor_sync(0xffffffffu, s2, o);
    }
    __shared__ float sh[16];
    int w = tid >> 5;
    if ((tid & 31) == 0) { sh[w] = s; sh[w + 8] = s2; }
    __syncthreads();
    if (tid == 0) {
        float a = 0.f, b2 = 0.f;
        #pragma unroll
        for (int i = 0; i < 8; i++) { a += sh[i]; b2 += sh[i + 8]; }
        sh[0] = a; sh[8] = b2;
    }
    __syncthreads();
    float mu  = sh[0] * (1.f / D_);
    float var = sh[8] * (1.f / D_) - mu * mu;
    float inv = rsqrtf(var + 1e-5f);
    size_t base = (size_t)row * D_;
    #pragma unroll
    for (int half = 0; half < 2; half++) {
        int c = tid + half * 256;
        float v = (half == 0 ? v0 : v1);
        float nv = (v - mu) * inv * gamma[c] + beta[c];
        __nv_bfloat16 hi = __float2bfloat16(nv);
        ohi[base + c] = hi;
        olo[base + c] = __float2bfloat16(nv - __bfloat162float(hi));
    }
}

__global__ void tsplit_kernel(const float* __restrict__ W, __nv_bfloat16* __restrict__ Thi,
                              __nv_bfloat16* __restrict__ Tlo, int K, int N) {
    int idx = blockIdx.x * 256 + threadIdx.x;
    if (idx >= K * N) return;
    int k = idx / N, n = idx % N;
    float v = W[idx];
    __nv_bfloat16 hi = __float2bfloat16(v);
    Thi[(size_t)n * K + k] = hi;
    Tlo[(size_t)n * K + k] = __float2bfloat16(v - __bfloat162float(hi));
}
__global__ void vtrans_kernel(const float* __restrict__ v, __nv_bfloat16* __restrict__ vth,
                              __nv_bfloat16* __restrict__ vtl) {
    __shared__ float ts[64][68];
    int bh = blockIdx.y, k0 = blockIdx.x * 64;
    int tid = threadIdx.x;
    const float* vb = v + ((size_t)bh * NTOK + k0) * DH_;
    #pragma unroll
    for (int i = 0; i < 4; i++) {
        int lin = tid + i * 256;
        int r = lin >> 4, c4 = lin & 15;
        *(float4*)&ts[r][c4 * 4] = *(const float4*)(vb + r * 64 + c4 * 4);
    }
    __syncthreads();
    #pragma unroll
    for (int i = 0; i < 16; i++) {
        int lin = tid + i * 256;
        int dh = lin >> 6, ky = lin & 63;
        float val = ts[ky][dh];
        __nv_bfloat16 h = __float2bfloat16(val);
        size_t o = ((size_t)bh * 64 + dh) * NTOK + k0 + ky;
        vth[o] = h;
        vtl[o] = __float2bfloat16(val - __bfloat162float(h));
    }
}
__global__ void ytrans_kernel(const float* __restrict__ Y, __nv_bfloat16* __restrict__ yth,
                              __nv_bfloat16* __restrict__ ytl) {
    int bh = blockIdx.x, tid = threadIdx.x;
    #pragma unroll
    for (int i = 0; i < 64; i++) {
        int lin = tid + i * 256;
        int dh = lin >> 8, lm = lin & 255;
        float val = Y[(size_t)bh * 16384 + lm * 64 + dh];
        __nv_bfloat16 h = __float2bfloat16(val);
        size_t o = (size_t)bh * 16384 + dh * 256 + lm;
        yth[o] = h;
        ytl[o] = __float2bfloat16(val - __bfloat162float(h));
    }
}

// ---- shared GEMM tile mainloop ----
template<int NPASS>
__device__ __forceinline__ void gemm_tile_main(
        uint32_t sbase, int tid, int wid, int lane, int wm, int wn,
        const __nv_bfloat16* Ahi, const __nv_bfloat16* Alo,
        const __nv_bfloat16* Bhi, const __nv_bfloat16* Blo,
        int kdim, int m0, int n0, float (&acc)[2][8][4])
{
    const __nv_bfloat16* srcs[4] = {Ahi, Alo, Bhi, Blo};
    const int row0s[4] = {m0, m0, n0, n0};
    const int NB = (NPASS == 1) ? 2 : 4;
    int r_ld = tid >> 2, c_ld = tid & 3;
    int nch = kdim >> 5;
    #pragma unroll
    for (int bs = 0; bs < NB; bs++) {
        int bsel = (NPASS == 1) ? bs * 2 : bs;
        #pragma unroll
        for (int i = 0; i < 2; i++)
            cp_async16(sbase + (uint32_t)(bsel * 5120 + (r_ld + i * 64) * 40 + c_ld * 8) * 2,
                       srcs[bsel] + (size_t)(row0s[bsel] + r_ld + i * 64) * kdim + c_ld * 8);
    }
    CP_COMMIT();
    for (int ch = 0; ch < nch; ch++) {
        CP_WAIT0();
        __syncthreads();
        if (ch + 1 < nch) {
            int k0 = (ch + 1) << 5;
            uint32_t nxt_off = (uint32_t)((ch + 1) & 1) * 4 * 5120;
            #pragma unroll
            for (int bs = 0; bs < NB; bs++) {
                int bsel = (NPASS == 1) ? bs * 2 : bs;
                #pragma unroll
                for (int i = 0; i < 2; i++)
                    cp_async16(sbase + (uint32_t)(nxt_off + bsel * 5120 + (r_ld + i * 64) * 40 + c_ld * 8) * 2,
                               srcs[bsel] + (size_t)(row0s[bsel] + r_ld + i * 64) * kdim + k0 + c_ld * 8);
            }
            CP_COMMIT();
        }
        uint32_t stg_off = (uint32_t)(ch & 1) * 4 * 5120;
        #pragma unroll
        for (int ks = 0; ks < 32; ks += 16) {
            uint32_t Ah[2][4], Al[2][4];
            #pragma unroll
            for (int mf = 0; mf < 2; mf++) {
                int row = wm + mf * 16 + (lane & 15);
                int col = ks + ((lane >> 4) << 3);
                ldsm4(Ah[mf], sbase + (uint32_t)(stg_off + row * 40 + col) * 2);
                if (NPASS > 1) ldsm4(Al[mf], sbase + (uint32_t)(stg_off + 5120 + row * 40 + col) * 2);
            }
            #pragma unroll
            for (int p = 0; p < 4; p++) {
                int rowb = wn + (2 * p + (lane >> 4)) * 8 + (lane & 7);
                int colb = ks + ((lane >> 3) & 1) * 8;
                uint32_t Bh4[4], Bl4[4];
                ldsm4(Bh4, sbase + (uint32_t)(stg_off + 2 * 5120 + rowb * 40 + colb) * 2);
                if (NPASS > 1) ldsm4(Bl4, sbase + (uint32_t)(stg_off + 3 * 5120 + rowb * 40 + colb) * 2);
                #pragma unroll
                for (int mf = 0; mf < 2; mf++) {
                    mma_bf16p(acc[mf][2*p],   Ah[mf], Bh4[0], Bh4[1]);
                    mma_bf16p(acc[mf][2*p+1], Ah[mf], Bh4[2], Bh4[3]);
                    if (NPASS > 1) {
                        mma_bf16p(acc[mf][2*p],   Ah[mf], Bl4[0], Bl4[1]);
                        mma_bf16p(acc[mf][2*p+1], Ah[mf], Bl4[2], Bl4[3]);
                        mma_bf16p(acc[mf][2*p],   Al[mf], Bh4[0], Bh4[1]);
                        mma_bf16p(acc[mf][2*p+1], Al[mf], Bh4[2], Bh4[3]);
                    }
                }
            }
        }
    }
    __syncthreads();
}

__device__ __forceinline__ void stage_acc(char* smem, int tid, int wid, int lane, int wm, int wn,
                                          float (&acc)[2][8][4]) {
    float* stg = reinterpret_cast<float*>(smem);
    int r = lane >> 2, c = (lane & 3) * 2;
    #pragma unroll
    for (int mf = 0; mf < 2; mf++)
        #pragma unroll
        for (int nf = 0; nf < 8; nf++) {
            int rr = wm + mf * 16 + r, cc = wn + nf * 8 + c;
            *reinterpret_cast<float2*>(&stg[rr * 132 + cc]) = make_float2(acc[mf][nf][0], acc[mf][nf][1]);
            *reinterpret_cast<float2*>(&stg[(rr + 8) * 132 + cc]) = make_float2(acc[mf][nf][2], acc[mf][nf][3]);
        }
    __syncthreads();
}

// ---- standalone GEMM kernel (modes 0/1) ----
#define TCG_SMEM (2 * 4 * 5120 * 2)
template<int NPASS>
__global__ void __launch_bounds__(256, 2) tc_gemm(
        const __nv_bfloat16* __restrict__ Ahi, const __nv_bfloat16* __restrict__ Alo,
        const __nv_bfloat16* __restrict__ Bhi, const __nv_bfloat16* __restrict__ Blo,
        int K, int mode,
        float* __restrict__ qp, float* __restrict__ kp, float* __restrict__ vp,
        float* __restrict__ Cout, const float* __restrict__ bias, const float* __restrict__ addx,
        __nv_bfloat16* __restrict__ Nhi, __nv_bfloat16* __restrict__ Nlo,
        __nv_bfloat16* __restrict__ Thi, __nv_bfloat16* __restrict__ Tlo)
{
    extern __shared__ __align__(16) char smem[];
    uint32_t sbase = smem_to_u32(smem);
    int tid = threadIdx.x;
    int wid = tid >> 5, lane = tid & 31;
    int wm = (wid & 3) * 32, wn = (wid >> 2) * 64;
    int m0 = blockIdx.y * 128, n0 = blockIdx.x * 128;

    float acc[2][8][4];
    #pragma unroll
    for (int a = 0; a < 2; a++)
        #pragma unroll
        for (int b = 0; b < 8; b++)
            #pragma unroll
            for (int c = 0; c < 4; c++) acc[a][b][c] = 0.f;

    gemm_tile_main<NPASS>(sbase, tid, wid, lane, wm, wn, Ahi, Alo, Bhi, Blo, K, m0, n0, acc);
    stage_acc(smem, tid, wid, lane, wm, wn, acc);
    float* stg = reinterpret_cast<float*>(smem);

    if (mode == 0) {
        #pragma unroll 4
        for (int i = 0; i < 16; i++) {
            int lin = tid + (i << 8);
            int token = lin >> 5, c4 = lin & 31;
            int gn = n0 + (c4 << 2);
            float4 v = *reinterpret_cast<float4*>(&stg[token * 132 + (c4 << 2)]);
            int gmm = m0 + token;
            int b_ = gmm >> 13, n_ = gmm & 8191;
            int sec = gn >> 9, cc = gn & 511, h_ = cc >> 6, dh = cc & 63;
            size_t idx = ((((size_t)b_ * H_ + h_) * NTOK) + n_) * DH_ + dh;
            if (sec == 2) {
                *reinterpret_cast<float4*>(&vp[idx]) = v;
            } else {
                if (sec == 0) { v.x *= 0.125f; v.y *= 0.125f; v.z *= 0.125f; v.w *= 0.125f; }
                float* fp = (sec == 0) ? qp : kp;
                __nv_bfloat16* hp = (sec == 0) ? Nhi : Thi;
                __nv_bfloat16* lp = (sec == 0) ? Nlo : Tlo;
                *reinterpret_cast<float4*>(&fp[idx]) = v;
                float vv[4] = {v.x, v.y, v.z, v.w};
                __nv_bfloat16 hb[4], lb[4];
                #pragma unroll
                for (int t2 = 0; t2 < 4; t2++) {
                    hb[t2] = __float2bfloat16(vv[t2]);
                    lb[t2] = __float2bfloat16(vv[t2] - __bfloat162float(hb[t2]));
                }
                *reinterpret_cast<uint2*>(&hp[idx]) = *reinterpret_cast<uint2*>(hb);
                *reinterpret_cast<uint2*>(&lp[idx]) = *reinterpret_cast<uint2*>(lb);
            }
        }
    } else {
        #pragma unroll 4
        for (int i = 0; i < 16; i++) {
            int lin = tid + (i << 8);
            int token = lin >> 5, c4 = lin & 31;
            int gn = n0 + (c4 << 2);
            int gmm = m0 + token;
            float4 v = *reinterpret_cast<float4*>(&stg[token * 132 + (c4 << 2)]);
            float4 bb = *reinterpret_cast<const float4*>(&bias[gn]);
            float4 xx = *reinterpret_cast<const float4*>(&addx[(size_t)gmm * 512 + gn]);
            v.x += bb.x + xx.x; v.y += bb.y + xx.y; v.z += bb.z + xx.z; v.w += bb.w + xx.w;
            *reinterpret_cast<float4*>(&Cout[(size_t)gmm * 512 + gn]) = v;
        }
    }
}

// ---- persistent pinv ----
__device__ __forceinline__ void grid_barrier() {
    __syncthreads();
    if (threadIdx.x == 0) {
        __threadfence();
        unsigned gen = atomicAdd(&g_bar_gen, 0u);
        unsigned ticket = atomicAdd(&g_bar_count, 1u);
        if (ticket == 127u) {
            g_bar_count = 0u;
            __threadfence();
            atomicAdd(&g_bar_gen, 1u);
        } else {
            while (atomicAdd(&g_bar_gen, 0u) == gen) { }
        }
    }
    __syncthreads();
}

template<int NPASS>
__device__ __forceinline__ void pinv_stage(char* smem, uint32_t sbase,
        const __nv_bfloat16* Ahi, const __nv_bfloat16* Alo,
        const __nv_bfloat16* Bhi, const __nv_bfloat16* Blo,
        __nv_bfloat16* Nhi, __nv_bfloat16* Nlo,
        __nv_bfloat16* Thi, __nv_bfloat16* Tlo,
        float* Cf32, float alpha, float diagc, float beta,
        size_t oz, int m0, int n0)
{
    int tid = threadIdx.x;
    int wid = tid >> 5, lane = tid & 31;
    int wm = (wid & 3) * 32, wn = (wid >> 2) * 64;
    float acc[2][8][4];
    #pragma unroll
    for (int a = 0; a < 2; a++)
        #pragma unroll
        for (int b = 0; b < 8; b++)
            #pragma unroll
            for (int c = 0; c < 4; c++) acc[a][b][c] = 0.f;
    gemm_tile_main<NPASS>(sbase, tid, wid, lane, wm, wn,
        Ahi + oz, Alo + oz, Bhi + oz, Blo + oz, MLM, m0, n0, acc);
    stage_acc(smem, tid, wid, lane, wm, wn, acc);
    float* stg = reinterpret_cast<float*>(smem);
    if (Thi) {
        #pragma unroll 4
        for (int i = 0; i < 64; i++) {
            int idx = tid + (i << 8);
            int gn_l = idx >> 7, gm_l = idx & 127;
            int gmm = m0 + gm_l, gn = n0 + gn_l;
            float v = stg[gm_l * 132 + gn_l];
            float t = (gmm == gn ? diagc : 0.f) - beta * v;
            __nv_bfloat16 h = __float2bfloat16(t);
            Thi[oz + (size_t)gn * 256 + gmm] = h;
            Tlo[oz + (size_t)gn * 256 + gmm] = __float2bfloat16(t - __bfloat162float(h));
        }
    }
    if (Nhi) {
        #pragma unroll 4
        for (int i = 0; i < 16; i++) {
            int lin = tid + (i << 8);
            int token = lin >> 5, c4 = lin & 31;
            int gn = n0 + (c4 << 2);
            int gmm = m0 + token;
            float4 v = *reinterpret_cast<float4*>(&stg[token * 132 + (c4 << 2)]);
            float vv[4] = {v.x * alpha, v.y * alpha, v.z * alpha, v.w * alpha};
            __nv_bfloat16 h[4], l2[4];
            #pragma unroll
            for (int t2 = 0; t2 < 4; t2++) {
                h[t2] = __float2bfloat16(vv[t2]);
                l2[t2] = __float2bfloat16(vv[t2] - __bfloat162float(h[t2]));
            }
            *reinterpret_cast<uint2*>(&Nhi[oz + (size_t)gmm * 256 + gn]) = *reinterpret_cast<uint2*>(h);
            *reinterpret_cast<uint2*>(&Nlo[oz + (size_t)gmm * 256 + gn]) = *reinterpret_cast<uint2*>(l2);
        }
    }
    if (Cf32) {
        #pragma unroll 4
        for (int i = 0; i < 16; i++) {
            int lin = tid + (i << 8);
            int token = lin >> 5, c4 = lin & 31;
            int gn = n0 + (c4 << 2);
            int gmm = m0 + token;
            float4 v = *reinterpret_cast<float4*>(&stg[token * 132 + (c4 << 2)]);
            v.x *= alpha; v.y *= alpha; v.z *= alpha; v.w *= alpha;
            *reinterpret_cast<float4*>(&Cf32[oz + (size_t)gmm * 256 + gn]) = v;
        }
    }
    __syncthreads();
}

__global__ void __launch_bounds__(256, 2) pinv_persistent(
        const __nv_bfloat16* __restrict__ Xh, const __nv_bfloat16* __restrict__ Xl,
        __nv_bfloat16* __restrict__ Znh0, __nv_bfloat16* __restrict__ Znl0,
        __nv_bfloat16* __restrict__ Zth0, __nv_bfloat16* __restrict__ Ztl0,
        __nv_bfloat16* __restrict__ XZh, __nv_bfloat16* __restrict__ XZl,
        __nv_bfloat16* __restrict__ WtAh, __nv_bfloat16* __restrict__ WtAl,
        __nv_bfloat16* __restrict__ WtBh, __nv_bfloat16* __restrict__ WtBl,
        float* __restrict__ Zf)
{
    extern __shared__ __align__(16) char smem[];
    uint32_t sbase = smem_to_u32(smem);
    int b = blockIdx.x;
    size_t oz = (size_t)(b >> 2) * 65536;
    int m0 = ((b >> 1) & 1) * 128, n0 = (b & 1) * 128;
    const size_t SB = (size_t)BH * 65536;

    int cur = 0;
    for (int it = 0; it < 6; it++) {
        __nv_bfloat16* Znc = Znh0 + cur * SB; __nv_bfloat16* Znlc = Znl0 + cur * SB;
        __nv_bfloat16* Ztc = Zth0 + cur * SB; __nv_bfloat16* Ztlc = Ztl0 + cur * SB;
        int nxt = cur ^ 1;
        __nv_bfloat16* Znn = Znh0 + nxt * SB; __nv_bfloat16* Znln = Znl0 + nxt * SB;
        __nv_bfloat16* Ztn = Zth0 + nxt * SB; __nv_bfloat16* Ztln = Ztl0 + nxt * SB;
        if (it < 5) {
            pinv_stage<1>(smem, sbase, Xh, Xl, Ztc, Ztlc, XZh, XZl, WtAh, WtAl, nullptr, 1.f, 7.f, 1.f, oz, m0, n0);
            grid_barrier();
            pinv_stage<1>(smem, sbase, XZh, XZl, WtAh, WtAl, nullptr, nullptr, WtBh, WtBl, nullptr, 1.f, 15.f, 1.f, oz, m0, n0);
            grid_barrier();
            pinv_stage<1>(smem, sbase, XZh, XZl, WtBh, WtBl, nullptr, nullptr, WtAh, WtAl, nullptr, 1.f, 13.f, 1.f, oz, m0, n0);
            grid_barrier();
            pinv_stage<1>(smem, sbase, Znc, Znlc, WtAh, WtAl, Znn, Znln, Ztn, Ztln, nullptr, 0.25f, 0.f, -0.25f, oz, m0, n0);
            grid_barrier();
        } else {
            pinv_stage<2>(smem, sbase, Xh, Xl, Ztc, Ztlc, XZh, XZl, WtAh, WtAl, nullptr, 1.f, 7.f, 1.f, oz, m0, n0);
            grid_barrier();
            pinv_stage<2>(smem, sbase, XZh, XZl, WtAh, WtAl, nullptr, nullptr, WtBh, WtBl, nullptr, 1.f, 15.f, 1.f, oz, m0, n0);
            grid_barrier();
            pinv_stage<2>(smem, sbase, XZh, XZl, WtBh, WtBl, nullptr, nullptr, WtAh, WtAl, nullptr, 1.f, 13.f, 1.f, oz, m0, n0);
            grid_barrier();
            pinv_stage<2>(smem, sbase, Znc, Znlc, WtAh, WtAl, nullptr, nullptr, nullptr, nullptr, Zf, 0.25f, 0.f, -0.25f, oz, m0, n0);
        }
        cur = nxt;
    }
}

// SIMT SGEMM for Y = Zf @ A3V
__global__ void __launch_bounds__(256) sgemm_kernel(
        const float* __restrict__ A, const float* __restrict__ B, float* __restrict__ C,
        int M, int N, int K, size_t sA, size_t sB, size_t sC)
{
    int bz = blockIdx.z;
    A += (size_t)bz * sA; B += (size_t)bz * sB; C += (size_t)bz * sC;
    int m0 = blockIdx.y * 128, n0 = blockIdx.x * 128;
    __shared__ float As[8][128];
    __shared__ float Bs[8][128];
    int tid = threadIdx.x;
    int tx = tid & 15, ty = tid >> 4;
    float acc[8][8];
    #pragma unroll
    for (int i = 0; i < 8; i++)
        #pragma unroll
        for (int j = 0; j < 8; j++) acc[i][j] = 0.f;
    for (int k0 = 0; k0 < K; k0 += 8) {
        #pragma unroll
        for (int i = 0; i < 4; i++) {
            int lin = tid + i * 256;
            int kk = lin & 7, mm = lin >> 3;
            int gmm = m0 + mm, gk = k0 + kk;
            As[kk][mm] = (gmm < M && gk < K) ? A[(size_t)gmm * K + gk] : 0.f;
        }
        #pragma unroll
        for (int i = 0; i < 4; i++) {
            int lin = tid + i * 256;
            int nn = lin & 127, kk = lin >> 7;
            int gn = n0 + nn, gk = k0 + kk;
            Bs[kk][nn] = (gn < N && gk < K) ? B[(size_t)gk * N + gn] : 0.f;
        }
        __syncthreads();
        #pragma unroll
        for (int kk = 0; kk < 8; kk++) {
            float a[8], b[8];
            *(float4*)&a[0] = *(const float4*)&As[kk][ty * 8];
            *(float4*)&a[4] = *(const float4*)&As[kk][ty * 8 + 4];
            *(float4*)&b[0] = *(const float4*)&Bs[kk][tx * 8];
            *(float4*)&b[4] = *(const float4*)&Bs[kk][tx * 8 + 4];
            #pragma unroll
            for (int i = 0; i < 8; i++)
                #pragma unroll
                for (int j = 0; j < 8; j++) acc[i][j] += a[i] * b[j];
        }
        __syncthreads();
    }
    #pragma unroll
    for (int i = 0; i < 8; i++) {
        int gmm = m0 + ty * 8 + i;
        if (gmm >= M) continue;
        #pragma unroll
        for (int j = 0; j < 8; j++) {
            int gn = n0 + tx * 8 + j;
            if (gn >= N) continue;
            C[(size_t)gmm * N + gn] = acc[i][j];
        }
    }
}

__global__ void landmark_kernel(const float* __restrict__ q, const float* __restrict__ k,
                                float* __restrict__ ql, float* __restrict__ kl,
                                __nv_bfloat16* __restrict__ qlh, __nv_bfloat16* __restrict__ qll,
                                __nv_bfloat16* __restrict__ klh, __nv_bfloat16* __restrict__ kll) {
    int bh = blockIdx.x, m = blockIdx.y;
    int dh = threadIdx.x;
    size_t base = ((size_t)bh * NTOK + (size_t)m * LSEG) * DH_ + dh;
    float aq = 0.f, ak = 0.f;
    #pragma unroll
    for (int i = 0; i < LSEG; i++) {
        aq += q[base + (size_t)i * DH_];
        ak += k[base + (size_t)i * DH_];
    }
    size_t o = ((size_t)bh * MLM + m) * DH_ + dh;
    float qv = aq * (1.f / LSEG), kv = ak * (1.f / LSEG);
    ql[o] = qv; kl[o] = kv;
    __nv_bfloat16 qh = __float2bfloat16(qv);
    qlh[o] = qh; qll[o] = __float2bfloat16(qv - __bfloat162float(qh));
    __nv_bfloat16 kh = __float2bfloat16(kv);
    klh[o] = kh; kll[o] = __float2bfloat16(kv - __bfloat162float(kh));
}

#define ATTN2_SMEM ((256 * 68 + 32 * 64 + 8) * 4)
__global__ void attn2_kernel(const float* __restrict__ ql, const float* __restrict__ kl,
                             float* __restrict__ X,
                             __nv_bfloat16* __restrict__ Xh, __nv_bfloat16* __restrict__ Xl) {
    extern __shared__ __align__(16) float sh2[];
    float* kls  = sh2;
    float* qs   = sh2 + 256 * 68;
    float* wsum = qs + 32 * 64;
    int bh = blockIdx.x, mt = blockIdx.y;
    int tid = threadIdx.x;
    #pragma unroll
    for (int i = 0; i < 16; i++) {
        int lin = tid + i * 256;
        int r = lin >> 4, c = lin & 15;
        *(float4*)&kls[r * 68 + c * 4] = *(const float4*)&kl[((size_t)bh * MLM + r) * DH_ + c * 4];
    }
    #pragma unroll
    for (int i = 0; i < 2; i++) {
        int lin = tid + i * 256;
        int r = lin >> 4, c = lin & 15;
        *(float4*)&qs[r * 64 + c * 4] = *(const float4*)&ql[((size_t)bh * MLM + mt * 32 + r) * DH_ + c * 4];
    }
    __syncthreads();
    int j = tid, wid = tid >> 5, lane = tid & 31;
    const float* kr = &kls[j * 68];
    for (int ml = 0; ml < 32; ml++) {
        const float* qr = &qs[ml * 64];
        float a0 = 0.f, a1 = 0.f, a2 = 0.f, a3 = 0.f;
        #pragma unroll
        for (int d4 = 0; d4 < 16; d4++) {
            float4 kv = *(const float4*)&kr[d4 * 4];
            float4 qv = *(const float4*)&qr[d4 * 4];
            a0 += qv.x * kv.x; a1 += qv.y * kv.y; a2 += qv.z * kv.z; a3 += qv.w * kv.w;
        }
        float e = fexp(a0 + a1 + a2 + a3);
        float t = e;
        #pragma unroll
        for (int o = 16; o > 0; o >>= 1) t += __shfl_xor_sync(0xffffffffu, t, o);
        if (lane == 0) wsum[wid] = t;
        __syncthreads();
        float S = 0.f;
        #pragma unroll
        for (int w = 0; w < 8; w++) S += wsum[w];
        float val = e * (1.f / S);
        size_t o = ((size_t)bh * MLM + mt * 32 + ml) * MLM + j;
        X[o] = val;
        __nv_bfloat16 h = __float2bfloat16(val);
        Xh[o] = h;
        Xl[o] = __float2bfloat16(val - __bfloat162float(h));
        __syncthreads();
    }
}

__global__ void initmax_kernel(unsigned* mb) { mb[0] = 0u; mb[1] = 0u; g_bar_count = 0u; g_bar_gen = 0u; }
__global__ void rowcol_kernel(const float* __restrict__ X, unsigned* mb) {
    int bh = blockIdx.x, i = threadIdx.x;
    const float* Xm = X + (size_t)bh * MLM * MLM;
    float rs = 0.f, cs = 0.f;
    for (int j = 0; j < MLM; j++) {
        rs += fabsf(Xm[(size_t)i * MLM + j]);
        cs += fabsf(Xm[(size_t)j * MLM + i]);
    }
    #pragma unroll
    for (int o = 16; o > 0; o >>= 1) {
        rs = fmaxf(rs, __shfl_xor_sync(0xffffffffu, rs, o));
        cs = fmaxf(cs, __shfl_xor_sync(0xffffffffu, cs, o));
    }
    __shared__ float shr[8], shc[8];
    int w = i >> 5;
    if ((i & 31) == 0) { shr[w] = rs; shc[w] = cs; }
    __syncthreads();
    if (i == 0) {
        float mr = shr[0], mc = shc[0];
        #pragma unroll
        for (int k2 = 1; k2 < 8; k2++) { mr = fmaxf(mr, shr[k2]); mc = fmaxf(mc, shc[k2]); }
        atomicMax(&mb[0], __float_as_uint(mr));
        atomicMax(&mb[1], __float_as_uint(mc));
    }
}
__global__ void zinit_kernel(const float* __restrict__ X, const unsigned* __restrict__ mb,
                             __nv_bfloat16* __restrict__ Znh, __nv_bfloat16* __restrict__ Znl,
                             __nv_bfloat16* __restrict__ Zth, __nv_bfloat16* __restrict__ Ztl) {
    float inv = 1.f / (__uint_as_float(mb[0]) * __uint_as_float(mb[1]));
    size_t idx = (size_t)blockIdx.x * 256 + threadIdx.x;
    int bh = (int)(idx >> 16);
    int r = (int)((idx >> 8) & 255);
    int c = (int)(idx & 255);
    float tv = X[idx] * inv;
    __nv_bfloat16 th = __float2bfloat16(tv);
    Zth[idx] = th; Ztl[idx] = __float2bfloat16(tv - __bfloat162float(th));
    float nv = X[((size_t)bh << 16) + ((size_t)c << 8) + r] * inv;
    __nv_bfloat16 nh = __float2bfloat16(nv);
    Znh[idx] = nh; Znl[idx] = __float2bfloat16(nv - __bfloat162float(nh));
}

// attn3@v via MMA, cp.async double-buffered k/v tiles.
#define A3_SMEM ((36864 + 2 * 9728) * 2)
__global__ void __launch_bounds__(256, 1) attn3v_mma(
        const __nv_bfloat16* __restrict__ qlh_, const __nv_bfloat16* __restrict__ qll_,
        const __nv_bfloat16* __restrict__ kh_, const __nv_bfloat16* __restrict__ klo_,
        const __nv_bfloat16* __restrict__ vth_, const __nv_bfloat16* __restrict__ vtl_,
        float* __restrict__ Opart, float* __restrict__ denpart)
{
    extern __shared__ __align__(16) __nv_bfloat16 sm3[];
    uint32_t sb = smem_to_u32(sm3);
    int tid = threadIdx.x, wid = tid >> 5, lane = tid & 31;
    int chunk = blockIdx.x, bh = blockIdx.y;
    int key0 = chunk * (NTOK / NCHK);
    {
        size_t qb = (size_t)bh * MLM * DH_;
        #pragma unroll
        for (int i = 0; i < 8; i++) {
            int lin = tid + i * 256;
            int r = lin >> 3, c = lin & 7;
            *(uint4*)(sm3 + r * 72 + c * 8) = *(const uint4*)(qlh_ + qb + r * 64 + c * 8);
            *(uint4*)(sm3 + 18432 + r * 72 + c * 8) = *(const uint4*)(qll_ + qb + r * 64 + c * 8);
        }
    }
    __syncthreads();
    uint32_t Ah[2][4][4], Al[2][4][4];
    #pragma unroll
    for (int mf = 0; mf < 2; mf++) {
        int row = wid * 32 + mf * 16 + (lane & 15);
        #pragma unroll
        for (int ks = 0; ks < 4; ks++) {
            int col = ks * 16 + ((lane >> 4) << 3);
            ldsm4(Ah[mf][ks], sb + (uint32_t)(row * 72 + col) * 2);
            ldsm4(Al[mf][ks], sb + (uint32_t)(18432 + row * 72 + col) * 2);
        }
    }
    float Oacc[2][8][4];
    #pragma unroll
    for (int a = 0; a < 2; a++)
        #pragma unroll
        for (int b = 0; b < 8; b++)
            #pragma unroll
            for (int c = 0; c < 4; c++) Oacc[a][b][c] = 0.f;
    float den[2][2] = {{0.f, 0.f}, {0.f, 0.f}};

    int r_k = tid >> 3, c_k = tid & 7;
    int r_v = tid >> 2, c_v = tid & 3;
    const int NIT = (NTOK / NCHK) / 32;

    {
        int kt0 = key0;
        uint32_t s0 = 36864;
        cp_async16(sb + (uint32_t)(s0 + r_k * 72 + c_k * 8) * 2,
                   kh_ + ((size_t)bh * NTOK + kt0 + r_k) * 64 + c_k * 8);
        cp_async16(sb + (uint32_t)(s0 + 2304 + r_k * 72 + c_k * 8) * 2,
                   klo_ + ((size_t)bh * NTOK + kt0 + r_k) * 64 + c_k * 8);
        cp_async16(sb + (uint32_t)(s0 + 4608 + r_v * 40 + c_v * 8) * 2,
                   vth_ + ((size_t)bh * 64 + r_v) * NTOK + kt0 + c_v * 8);
        cp_async16(sb + (uint32_t)(s0 + 7168 + r_v * 40 + c_v * 8) * 2,
                   vtl_ + ((size_t)bh * 64 + r_v) * NTOK + kt0 + c_v * 8);
    }
    CP_COMMIT();

    for (int t32 = 0; t32 < NIT; t32++) {
        CP_WAIT0();
        __syncthreads();
        if (t32 + 1 < NIT) {
            int kt1 = key0 + (t32 + 1) * 32;
            uint32_t sn = 36864 + (uint32_t)((t32 + 1) & 1) * 9728;
            cp_async16(sb + (uint32_t)(sn + r_k * 72 + c_k * 8) * 2,
                       kh_ + ((size_t)bh * NTOK + kt1 + r_k) * 64 + c_k * 8);
            cp_async16(sb + (uint32_t)(sn + 2304 + r_k * 72 + c_k * 8) * 2,
                       klo_ + ((size_t)bh * NTOK + kt1 + r_k) * 64 + c_k * 8);
            cp_async16(sb + (uint32_t)(sn + 4608 + r_v * 40 + c_v * 8) * 2,
                       vth_ + ((size_t)bh * 64 + r_v) * NTOK + kt1 + c_v * 8);
            cp_async16(sb + (uint32_t)(sn + 7168 + r_v * 40 + c_v * 8) * 2,
                       vtl_ + ((size_t)bh * 64 + r_v) * NTOK + kt1 + c_v * 8);
            CP_COMMIT();
        }
        uint32_t kb = 36864 + (uint32_t)(t32 & 1) * 9728;
        uint32_t klb = kb + 2304, vhb = kb + 4608, vlb = kb + 7168;
        float S[2][4][4];
        #pragma unroll
        for (int a = 0; a < 2; a++)
            #pragma unroll
            for (int b = 0; b < 4; b++)
                #pragma unroll
                for (int c = 0; c < 4; c++) S[a][b][c] = 0.f;
        #pragma unroll
        for (int ks = 0; ks < 4; ks++) {
            #pragma unroll
            for (int np = 0; np < 2; np++) {
                int row = np * 16 + ((lane >> 4) & 1) * 8 + (lane & 7);
                int col = ks * 16 + ((lane >> 3) & 1) * 8;
                uint32_t bh4[4], bl4[4];
                ldsm4(bh4, sb + (uint32_t)(kb + row * 72 + col) * 2);
                ldsm4(bl4, sb + (uint32_t)(klb + row * 72 + col) * 2);
                #pragma unroll
                for (int mf = 0; mf < 2; mf++) {
                    mma_bf16p(S[mf][2*np],   Ah[mf][ks], bh4[0], bh4[1]);
                    mma_bf16p(S[mf][2*np],   Ah[mf][ks], bl4[0], bl4[1]);
                    mma_bf16p(S[mf][2*np],   Al[mf][ks], bh4[0], bh4[1]);
                    mma_bf16p(S[mf][2*np+1], Ah[mf][ks], bh4[2], bh4[3]);
                    mma_bf16p(S[mf][2*np+1], Ah[mf][ks], bl4[2], bl4[3]);
                    mma_bf16p(S[mf][2*np+1], Al[mf][ks], bh4[2], bh4[3]);
                }
            }
        }
        #pragma unroll
        for (int kt = 0; kt < 2; kt++) {
            uint32_t pah[2][4], pal[2][4];
            #pragma unroll
            for (int mf = 0; mf < 2; mf++) {
                float e[8];
                #pragma unroll
                for (int j = 0; j < 4; j++) { e[j] = fexp(S[mf][2*kt][j]); e[4+j] = fexp(S[mf][2*kt+1][j]); }
                den[mf][0] += e[0] + e[1] + e[4] + e[5];
                den[mf][1] += e[2] + e[3] + e[6] + e[7];
                #pragma unroll
                for (int j = 0; j < 4; j++) {
                    __nv_bfloat162 h2 = __floats2bfloat162_rn(e[2*j], e[2*j+1]);
                    pah[mf][j] = *(uint32_t*)&h2;
                    float r0 = e[2*j]   - __bfloat162float(__low2bfloat16(h2));
                    float r1 = e[2*j+1] - __bfloat162float(__high2bfloat16(h2));
                    __nv_bfloat162 l2 = __floats2bfloat162_rn(r0, r1);
                    pal[mf][j] = *(uint32_t*)&l2;
                }
            }
            #pragma unroll
            for (int np = 0; np < 4; np++) {
                int row = np * 16 + ((lane >> 4) & 1) * 8 + (lane & 7);
                int col = kt * 16 + ((lane >> 3) & 1) * 8;
                uint32_t vh4[4], vl4[4];
                ldsm4(vh4, sb + (uint32_t)(vhb + row * 40 + col) * 2);
                ldsm4(vl4, sb + (uint32_t)(vlb + row * 40 + col) * 2);
                #pragma unroll
                for (int mf = 0; mf < 2; mf++) {
                    mma_bf16p(Oacc[mf][2*np],   pah[mf], vh4[0], vh4[1]);
                    mma_bf16p(Oacc[mf][2*np],   pah[mf], vl4[0], vl4[1]);
                    mma_bf16p(Oacc[mf][2*np],   pal[mf], vh4[0], vh4[1]);
                    mma_bf16p(Oacc[mf][2*np+1], pah[mf], vh4[2], vh4[3]);
                    mma_bf16p(Oacc[mf][2*np+1], pah[mf], vl4[2], vl4[3]);
                    mma_bf16p(Oacc[mf][2*np+1], pal[mf], vh4[2], vh4[3]);
                }
            }
        }
    }
    #pragma unroll
    for (int mf = 0; mf < 2; mf++)
        #pragma unroll
        for (int j = 0; j < 2; j++) {
            den[mf][j] += __shfl_xor_sync(0xffffffffu, den[mf][j], 1);
            den[mf][j] += __shfl_xor_sync(0xffffffffu, den[mf][j], 2);
        }
    int g = lane >> 2, t = lane & 3;
    size_t ob = ((size_t)chunk * BH + bh) * MLM * 64;
    #pragma unroll
    for (int mf = 0; mf < 2; mf++) {
        int lm0 = wid * 32 + mf * 16 + g;
        #pragma unroll
        for (int nf = 0; nf < 8; nf++) {
            int c = nf * 8 + t * 2;
            *(float2*)&Opart[ob + (size_t)lm0 * 64 + c] = make_float2(Oacc[mf][nf][0], Oacc[mf][nf][1]);
            *(float2*)&Opart[ob + (size_t)(lm0 + 8) * 64 + c] = make_float2(Oacc[mf][nf][2], Oacc[mf][nf][3]);
        }
        if (t == 0) {
            denpart[((size_t)chunk * BH + bh) * MLM + lm0] = den[mf][0];
            denpart[((size_t)chunk * BH + bh) * MLM + lm0 + 8] = den[mf][1];
        }
    }
}

__global__ void a3v_reduce(const float* __restrict__ Opart, const float* __restrict__ denpart,
                           float* __restrict__ A3V) {
    int idx = blockIdx.x * 256 + threadIdx.x;
    int bh = idx >> 14, lm = (idx >> 6) & 255;
    float s = 0.f, d = 0.f;
    #pragma unroll
    for (int c = 0; c < NCHK; c++) {
        s += Opart[((size_t)c * BH + bh) * 16384 + (idx & 16383)];
        d += denpart[((size_t)c * BH + bh) * 256 + lm];
    }
    A3V[idx] = s / d;
}

// attn1 + conv + osplit fused; v-halo load overlapped with MMA via cp.async groups
#define A1V_OFF  89088
#define A1KW_OFF (178176 + 43520)
#define A1_SMEM  (178176 + 43520 + 256)
__global__ void __launch_bounds__(256, 1) attn1_mma(
        const __nv_bfloat16* __restrict__ qh_, const __nv_bfloat16* __restrict__ qlo_,
        const __nv_bfloat16* __restrict__ klh_, const __nv_bfloat16* __restrict__ kll_,
        const __nv_bfloat16* __restrict__ yth_, const __nv_bfloat16* __restrict__ ytl_,
        const float* __restrict__ v_, const float* __restrict__ ker,
        __nv_bfloat16* __restrict__ Ohi, __nv_bfloat16* __restrict__ Olo)
{
    extern __shared__ __align__(16) __nv_bfloat16 sm1[];
    uint32_t sb = smem_to_u32(sm1);
    float* vs = reinterpret_cast<float*>(sm1 + A1V_OFF);
    float* kw = reinterpret_cast<float*>((char*)sm1 + A1KW_OFF);
    int tid = threadIdx.x, wid = tid >> 5, lane = tid & 31;
    int bh = blockIdx.y;
    int b = bh >> 3, h = bh & 7;
    {
        size_t kb = (size_t)bh * MLM * DH_;
        #pragma unroll
        for (int i = 0; i < 8; i++) {
            int lin = tid + i * 256;
            int r = lin >> 3, c = lin & 7;
            *(uint4*)(sm1 + 18432 + r * 72 + c * 8) = *(const uint4*)(klh_ + kb + r * 64 + c * 8);
            *(uint4*)(sm1 + 36864 + r * 72 + c * 8) = *(const uint4*)(kll_ + kb + r * 64 + c * 8);
        }
        size_t yb = (size_t)bh * 64 * MLM;
        #pragma unroll
        for (int i = 0; i < 8; i++) {
            int lin = tid + i * 256;
            int r = lin >> 5, c = lin & 31;
            *(uint4*)(sm1 + 55296 + r * 264 + c * 8) = *(const uint4*)(yth_ + yb + r * 256 + c * 8);
            *(uint4*)(sm1 + 72192 + r * 264 + c * 8) = *(const uint4*)(ytl_ + yb + r * 256 + c * 8);
        }
        if (tid < KER_) kw[tid] = ker[h * KER_ + tid];
    }
    const float* vb = v_ + ((size_t)b * H_ + h) * NTOK * DH_;

    for (int tt = 0; tt < A1_TPB; tt++) {
        int tile0 = (blockIdx.x * A1_TPB + tt) * 128;
        __syncthreads();   // prior tile done with q & v buffers
        {
            // group 0: q tile (needed immediately)
            size_t qb = ((size_t)bh * NTOK + tile0) * DH_;
            #pragma unroll
            for (int i = 0; i < 4; i++) {
                int lin = tid + i * 256;
                int r = lin >> 3, c = lin & 7;
                cp_async16(sb + (uint32_t)(r * 72 + c * 8) * 2, qh_ + qb + (size_t)r * 64 + c * 8);
                cp_async16(sb + (uint32_t)(9216 + r * 72 + c * 8) * 2, qlo_ + qb + (size_t)r * 64 + c * 8);
            }
            CP_COMMIT();
            // group 1: v halo (needed only at epilogue)
            #pragma unroll
            for (int i = 0; i < 10; i++) {
                int f4 = tid + i * 256;
                int row = f4 >> 4, c4 = f4 & 15;
                int n = tile0 - 16 + row;
                if (n >= 0 && n < NTOK)
                    cp_async16(sb + (uint32_t)(A1V_OFF * 2 + (row * 68 + c4 * 4) * 4),
                               vb + (size_t)n * DH_ + c4 * 4);
                else
                    *(float4*)&vs[row * 68 + c4 * 4] = make_float4(0.f, 0.f, 0.f, 0.f);
            }
            CP_COMMIT();
        }
        CP_WAIT1();          // q complete; v may still be in flight
        __syncthreads();
        uint32_t Ah[4][4], Al[4][4];
        {
            int row = wid * 16 + (lane & 15);
            #pragma unroll
            for (int ks = 0; ks < 4; ks++) {
                int col = ks * 16 + ((lane >> 4) << 3);
                ldsm4(Ah[ks], sb + (uint32_t)(row * 72 + col) * 2);
                ldsm4(Al[ks], sb + (uint32_t)(9216 + row * 72 + col) * 2);
            }
        }
        float Oacc[8][4];
        #pragma unroll
        for (int bb = 0; bb < 8; bb++)
            #pragma unroll
            for (int c = 0; c < 4; c++) Oacc[bb][c] = 0.f;
        float dlo = 0.f, dhi = 0.f;

        #pragma unroll
        for (int half = 0; half < 2; half++) {
            int lmb = half * 128;
            float S[16][4];
            #pragma unroll
            for (int bb = 0; bb < 16; bb++)
                #pragma unroll
                for (int c = 0; c < 4; c++) S[bb][c] = 0.f;
            #pragma unroll
            for (int ks = 0; ks < 4; ks++) {
                #pragma unroll
                for (int np = 0; np < 8; np++) {
                    int row = lmb + np * 16 + ((lane >> 4) & 1) * 8 + (lane & 7);
                    int col = ks * 16 + ((lane >> 3) & 1) * 8;
                    uint32_t bh4[4], bl4[4];
                    ldsm4(bh4, sb + (uint32_t)(18432 + row * 72 + col) * 2);
                    ldsm4(bl4, sb + (uint32_t)(36864 + row * 72 + col) * 2);
                    mma_bf16p(S[2*np],   Ah[ks], bh4[0], bh4[1]);
                    mma_bf16p(S[2*np],   Ah[ks], bl4[0], bl4[1]);
                    mma_bf16p(S[2*np],   Al[ks], bh4[0], bh4[1]);
                    mma_bf16p(S[2*np+1], Ah[ks], bh4[2], bh4[3]);
                    mma_bf16p(S[2*np+1], Ah[ks], bl4[2], bl4[3]);
                    mma_bf16p(S[2*np+1], Al[ks], bh4[2], bh4[3]);
                }
            }
            #pragma unroll
            for (int kt = 0; kt < 8; kt++) {
                float e[8];
                #pragma unroll
                for (int j = 0; j < 4; j++) { e[j] = fexp(S[2*kt][j]); e[4+j] = fexp(S[2*kt+1][j]); }
                dlo += e[0] + e[1] + e[4] + e[5];
                dhi += e[2] + e[3] + e[6] + e[7];
                uint32_t pah[4], pal[4];
                #pragma unroll
                for (int j = 0; j < 4; j++) {
                    __nv_bfloat162 h2 = __floats2bfloat162_rn(e[2*j], e[2*j+1]);
                    pah[j] = *(uint32_t*)&h2;
                    float r0 = e[2*j]   - __bfloat162float(__low2bfloat16(h2));
                    float r1 = e[2*j+1] - __bfloat162float(__high2bfloat16(h2));
                    __nv_bfloat162 l2 = __floats2bfloat162_rn(r0, r1);
                    pal[j] = *(uint32_t*)&l2;
                }
                #pragma unroll
                for (int np = 0; np < 4; np++) {
                    int row = np * 16 + ((lane >> 4) & 1) * 8 + (lane & 7);
                    int col = lmb + kt * 16 + ((lane >> 3) & 1) * 8;
                    uint32_t yh4[4], yl4[4];
                    ldsm4(yh4, sb + (uint32_t)(55296 + row * 264 + col) * 2);
                    ldsm4(yl4, sb + (uint32_t)(72192 + row * 264 + col) * 2);
                    mma_bf16p(Oacc[2*np],   pah, yh4[0], yh4[1]);
                    mma_bf16p(Oacc[2*np],   pah, yl4[0], yl4[1]);
                    mma_bf16p(Oacc[2*np],   pal, yh4[0], yh4[1]);
                    mma_bf16p(Oacc[2*np+1], pah, yh4[2], yh4[3]);
                    mma_bf16p(Oacc[2*np+1], pah, yl4[2], yl4[3]);
                    mma_bf16p(Oacc[2*np+1], pal, yh4[2], yh4[3]);
                }
            }
        }
        CP_WAIT0();          // v halo now complete
        __syncthreads();
        dlo += __shfl_xor_sync(0xffffffffu, dlo, 1);
        dlo += __shfl_xor_sync(0xffffffffu, dlo, 2);
        dhi += __shfl_xor_sync(0xffffffffu, dhi, 1);
        dhi += __shfl_xor_sync(0xffffffffu, dhi, 2);
        float ilo = 1.f / dlo, ihi = 1.f / dhi;
        int g = lane >> 2, t = lane & 3;
        int tok0 = tile0 + wid * 16 + g;
        int r0 = wid * 16 + g;
        size_t ob = ((size_t)b * NTOK + tok0) * D_ + h * DH_;
        #pragma unroll
        for (int nf = 0; nf < 8; nf++) {
            int c = nf * 8 + t * 2;
            float cv00 = 0.f, cv01 = 0.f, cv10 = 0.f, cv11 = 0.f;
            #pragma unroll
            for (int tap = 0; tap < KER_; tap++) {
                float w = kw[tap];
                cv00 += w * vs[(r0 + tap) * 68 + c];
                cv01 += w * vs[(r0 + tap) * 68 + c + 1];
                cv10 += w * vs[(r0 + 8 + tap) * 68 + c];
                cv11 += w * vs[(r0 + 8 + tap) * 68 + c + 1];
            }
            float o00 = Oacc[nf][0] * ilo + cv00;
            float o01 = Oacc[nf][1] * ilo + cv01;
            float o10 = Oacc[nf][2] * ihi + cv10;
            float o11 = Oacc[nf][3] * ihi + cv11;
            __nv_bfloat162 h0 = __floats2bfloat162_rn(o00, o01);
            __nv_bfloat162 l0 = __floats2bfloat162_rn(o00 - __bfloat162float(__low2bfloat16(h0)),
                                                      o01 - __bfloat162float(__high2bfloat16(h0)));
            *(uint32_t*)&Ohi[ob + c] = *(uint32_t*)&h0;
            *(uint32_t*)&Olo[ob + c] = *(uint32_t*)&l0;
            __nv_bfloat162 h1 = __floats2bfloat162_rn(o10, o11);
            __nv_bfloat162 l1 = __floats2bfloat162_rn(o10 - __bfloat162float(__low2bfloat16(h1)),
                                                      o11 - __bfloat162float(__high2bfloat16(h1)));
            *(uint32_t*)&Ohi[ob + (size_t)8 * D_ + c] = *(uint32_t*)&h1;
            *(uint32_t*)&Olo[ob + (size_t)8 * D_ + c] = *(uint32_t*)&l1;
        }
    }
}

extern "C" void kernel_launch(void* const* d_in, const int* in_sizes, int n_in,
                              void* d_out, int out_size) {
    const float* x      = (const float*)d_in[0];
    const float* gamma  = (const float*)d_in[1];
    const float* beta   = (const float*)d_in[2];
    const float* w_qkv  = (const float*)d_in[3];
    const float* res_k  = (const float*)d_in[4];
    const float* w_out  = (const float*)d_in[5];
    const float* b_out  = (const float*)d_in[6];
    float* out = (float*)d_out;

    __nv_bfloat16 *nh, *nl, *wqh, *wql, *woh, *wol, *Oh, *Ol, *Xh, *Xl;
    __nv_bfloat16 *Znh, *Znl, *Zth, *Ztl, *XZh, *XZl, *WtAh, *WtAl, *WtBh, *WtBl;
    __nv_bfloat16 *qbh, *qbl, *kbh, *kbl, *vth, *vtl, *qlh, *qll, *klh, *kll, *yth, *ytl;
    float *q, *k, *v, *ql, *kl, *X, *Zf, *A3V, *Y, *Opart, *dpart;
    unsigned* mb;
    cudaGetSymbolAddress((void**)&nh, g_nh);
    cudaGetSymbolAddress((void**)&nl, g_nl);
    cudaGetSymbolAddress((void**)&wqh, g_wqh);
    cudaGetSymbolAddress((void**)&wql, g_wql);
    cudaGetSymbolAddress((void**)&woh, g_woh);
    cudaGetSymbolAddress((void**)&wol, g_wol);
    cudaGetSymbolAddress((void**)&Oh, g_Oh);
    cudaGetSymbolAddress((void**)&Ol, g_Ol);
    cudaGetSymbolAddress((void**)&Xh, g_Xh);
    cudaGetSymbolAddress((void**)&Xl, g_Xl);
    cudaGetSymbolAddress((void**)&Znh, g_Znh);
    cudaGetSymbolAddress((void**)&Znl, g_Znl);
    cudaGetSymbolAddress((void**)&Zth, g_Zth);
    cudaGetSymbolAddress((void**)&Ztl, g_Ztl);
    cudaGetSymbolAddress((void**)&XZh, g_XZh);
    cudaGetSymbolAddress((void**)&XZl, g_XZl);
    cudaGetSymbolAddress((void**)&WtAh, g_WtAh);
    cudaGetSymbolAddress((void**)&WtAl, g_WtAl);
    cudaGetSymbolAddress((void**)&WtBh, g_WtBh);
    cudaGetSymbolAddress((void**)&WtBl, g_WtBl);
    cudaGetSymbolAddress((void**)&q,  g_q);
    cudaGetSymbolAddress((void**)&k,  g_k);
    cudaGetSymbolAddress((void**)&v,  g_v);
    cudaGetSymbolAddress((void**)&qbh, g_qbh);
    cudaGetSymbolAddress((void**)&qbl, g_qbl);
    cudaGetSymbolAddress((void**)&kbh, g_kbh);
    cudaGetSymbolAddress((void**)&kbl, g_kbl);
    cudaGetSymbolAddress((void**)&vth, g_vth);
    cudaGetSymbolAddress((void**)&vtl, g_vtl);
    cudaGetSymbolAddress((void**)&ql, g_ql);
    cudaGetSymbolAddress((void**)&kl, g_kl);
    cudaGetSymbolAddress((void**)&qlh, g_qlh);
    cudaGetSymbolAddress((void**)&qll, g_qll);
    cudaGetSymbolAddress((void**)&klh, g_klh);
    cudaGetSymbolAddress((void**)&kll, g_kll);
    cudaGetSymbolAddress((void**)&yth, g_yth);
    cudaGetSymbolAddress((void**)&ytl, g_ytl);
    cudaGetSymbolAddress((void**)&X,  g_X);
    cudaGetSymbolAddress((void**)&Zf, g_Zf);
    cudaGetSymbolAddress((void**)&Opart, g_Opart);
    cudaGetSymbolAddress((void**)&dpart, g_dpart);
    cudaGetSymbolAddress((void**)&A3V, g_A3V);
    cudaGetSymbolAddress((void**)&Y,  g_Y);
    cudaGetSymbolAddress((void**)&mb, g_maxbits);

    cudaFuncSetAttribute(attn2_kernel, cudaFuncAttributeMaxDynamicSharedMemorySize, ATTN2_SMEM);
    cudaFuncSetAttribute(tc_gemm<2>, cudaFuncAttributeMaxDynamicSharedMemorySize, TCG_SMEM);
    cudaFuncSetAttribute(pinv_persistent, cudaFuncAttributeMaxDynamicSharedMemorySize, TCG_SMEM);
    cudaFuncSetAttribute(attn3v_mma, cudaFuncAttributeMaxDynamicSharedMemorySize, A3_SMEM);
    cudaFuncSetAttribute(attn1_mma, cudaFuncAttributeMaxDynamicSharedMemorySize, A1_SMEM);

    ln_kernel<<<B_ * NTOK, 256>>>(x, gamma, beta, nh, nl);
    tsplit_kernel<<<(D_ * 3 * D_ + 255) / 256, 256>>>(w_qkv, wqh, wql, D_, 3 * D_);
    tsplit_kernel<<<(D_ * D_ + 255) / 256, 256>>>(w_out, woh, wol, D_, D_);

    tc_gemm<2><<<dim3(12, 256, 1), 256, TCG_SMEM>>>(nh, nl, wqh, wql, D_, 0,
        q, k, v, nullptr, nullptr, nullptr, qbh, qbl, kbh, kbl);

    vtrans_kernel<<<dim3(NTOK / 64, BH), 256>>>(v, vth, vtl);
    landmark_kernel<<<dim3(BH, MLM), 64>>>(q, k, ql, kl, qlh, qll, klh, kll);

    attn2_kernel<<<dim3(BH, 8), 256, ATTN2_SMEM>>>(ql, kl, X, Xh, Xl);
    initmax_kernel<<<1, 1>>>(mb);
    rowcol_kernel<<<BH, 256>>>(X, mb);
    zinit_kernel<<<8192, 256>>>(X, mb, Znh, Znl, Zth, Ztl);

    pinv_persistent<<<128, 256, TCG_SMEM>>>(Xh, Xl, Znh, Znl, Zth, Ztl,
        XZh, XZl, WtAh, WtAl, WtBh, WtBl, Zf);

    attn3v_mma<<<dim3(NCHK, BH), 256, A3_SMEM>>>(qlh, qll, kbh, kbl, vth, vtl, Opart, dpart);
    a3v_reduce<<<2048, 256>>>(Opart, dpart, A3V);

    sgemm_kernel<<<dim3(1, 2, BH), 256>>>(Zf, A3V, Y, MLM, DH_, MLM,
        (size_t)MLM * MLM, (size_t)MLM * DH_, (size_t)MLM * DH_);
    ytrans_kernel<<<BH, 256>>>(Y, yth, ytl);

    attn1_mma<<<dim3(NTOK / 128 / A1_TPB, BH), 256, A1_SMEM>>>(
        qbh, qbl, klh, kll, yth, ytl, v, res_k, Oh, Ol);

    tc_gemm<2><<<dim3(4, 256, 1), 256, TCG_SMEM>>>(Oh, Ol, woh, wol, D_, 1,
        nullptr, nullptr, nullptr, out, b_out, x, nullptr, nullptr, nullptr, nullptr);
}

// round 17
// speedup vs baseline: 6.6201x; 1.0173x over previous
#include <cuda_runtime.h>
#include <cuda_bf16.h>
#include <math.h>
#include <stdint.h>

#define B_    4
#define NTOK  8192
#define D_    512
#define H_    8
#define DH_   64
#define MLM   256
#define LSEG  32
#define BH    (B_*H_)
#define KER_  33
#define NCHK  8
#define A1_TPB 4

__device__ __forceinline__ uint32_t smem_to_u32(const void* p) {
    uint32_t a;
    asm("{ .reg .u64 t; cvta.to.shared.u64 t, %1; cvt.u32.u64 %0, t; }" : "=r"(a) : "l"(p));
    return a;
}
__device__ __forceinline__ void cp_async16(uint32_t saddr, const void* gptr) {
    asm volatile("cp.async.cg.shared.global [%0], [%1], 16;" :: "r"(saddr), "l"(gptr));
}
#define CP_COMMIT() asm volatile("cp.async.commit_group;" ::: "memory")
#define CP_WAIT0()  asm volatile("cp.async.wait_group 0;" ::: "memory")
#define CP_WAIT1()  asm volatile("cp.async.wait_group 1;" ::: "memory")
__device__ __forceinline__ void mma_bf16p(float (&d)[4], const uint32_t (&a)[4], uint32_t b0, uint32_t b1) {
    asm volatile("mma.sync.aligned.m16n8k16.row.col.f32.bf16.bf16.f32 "
        "{%0,%1,%2,%3}, {%4,%5,%6,%7}, {%8,%9}, {%0,%1,%2,%3};"
        : "+f"(d[0]), "+f"(d[1]), "+f"(d[2]), "+f"(d[3])
        : "r"(a[0]), "r"(a[1]), "r"(a[2]), "r"(a[3]), "r"(b0), "r"(b1));
}
__device__ __forceinline__ void ldsm4(uint32_t (&r)[4], uint32_t a) {
    asm volatile("ldmatrix.sync.aligned.m8n8.x4.shared.b16 {%0,%1,%2,%3}, [%4];"
        : "=r"(r[0]), "=r"(r[1]), "=r"(r[2]), "=r"(r[3]) : "r"(a));
}
__device__ __forceinline__ float fexp(float s) {
    float t = s * 1.44269504088896341f;
    float i = rintf(t);
    float f = t - i;
    float p = 1.54035303933816e-4f;
    p = p * f + 1.33335581464284e-3f;
    p = p * f + 9.61812910762848e-3f;
    p = p * f + 5.55041086648216e-2f;
    p = p * f + 2.40226506959101e-1f;
    p = p * f + 6.93147180559945e-1f;
    p = p * f + 1.0f;
    return p * __int_as_float(((int)i + 127) << 23);
}

// scratch
__device__ __nv_bfloat16 g_nh[(size_t)B_*NTOK*D_];
__device__ __nv_bfloat16 g_nl[(size_t)B_*NTOK*D_];
__device__ __nv_bfloat16 g_wqh[(size_t)3*D_*D_];
__device__ __nv_bfloat16 g_wql[(size_t)3*D_*D_];
__device__ __nv_bfloat16 g_woh[(size_t)D_*D_];
__device__ __nv_bfloat16 g_wol[(size_t)D_*D_];
__device__ __nv_bfloat16 g_Oh[(size_t)B_*NTOK*D_];
__device__ __nv_bfloat16 g_Ol[(size_t)B_*NTOK*D_];
__device__ float g_q [(size_t)BH*NTOK*DH_];
__device__ float g_k [(size_t)BH*NTOK*DH_];
__device__ float g_v [(size_t)BH*NTOK*DH_];
__device__ __nv_bfloat16 g_qbh[(size_t)BH*NTOK*DH_];
__device__ __nv_bfloat16 g_qbl[(size_t)BH*NTOK*DH_];
__device__ __nv_bfloat16 g_kbh[(size_t)BH*NTOK*DH_];
__device__ __nv_bfloat16 g_kbl[(size_t)BH*NTOK*DH_];
__device__ __nv_bfloat16 g_vth[(size_t)BH*NTOK*DH_];
__device__ __nv_bfloat16 g_vtl[(size_t)BH*NTOK*DH_];
__device__ float g_ql[(size_t)BH*MLM*DH_];
__device__ float g_kl[(size_t)BH*MLM*DH_];
__device__ __nv_bfloat16 g_qlh[(size_t)BH*MLM*DH_];
__device__ __nv_bfloat16 g_qll[(size_t)BH*MLM*DH_];
__device__ __nv_bfloat16 g_klh[(size_t)BH*MLM*DH_];
__device__ __nv_bfloat16 g_kll[(size_t)BH*MLM*DH_];
__device__ __nv_bfloat16 g_yth[(size_t)BH*MLM*DH_];
__device__ __nv_bfloat16 g_ytl[(size_t)BH*MLM*DH_];
__device__ float g_X [(size_t)BH*MLM*MLM];
__device__ __nv_bfloat16 g_Xh[(size_t)BH*MLM*MLM];
__device__ __nv_bfloat16 g_Xl[(size_t)BH*MLM*MLM];
__device__ __nv_bfloat16 g_Znh[2][(size_t)BH*MLM*MLM];
__device__ __nv_bfloat16 g_Znl[2][(size_t)BH*MLM*MLM];
__device__ __nv_bfloat16 g_Zth[2][(size_t)BH*MLM*MLM];
__device__ __nv_bfloat16 g_Ztl[2][(size_t)BH*MLM*MLM];
__device__ __nv_bfloat16 g_XZh[(size_t)BH*MLM*MLM];
__device__ __nv_bfloat16 g_XZl[(size_t)BH*MLM*MLM];
__device__ __nv_bfloat16 g_WtAh[(size_t)BH*MLM*MLM];
__device__ __nv_bfloat16 g_WtAl[(size_t)BH*MLM*MLM];
__device__ __nv_bfloat16 g_WtBh[(size_t)BH*MLM*MLM];
__device__ __nv_bfloat16 g_WtBl[(size_t)BH*MLM*MLM];
__device__ float g_Opart[(size_t)NCHK*BH*MLM*DH_];
__device__ float g_dpart[(size_t)NCHK*BH*MLM];
__device__ __nv_bfloat16 g_a3h[(size_t)BH*128*MLM];
__device__ __nv_bfloat16 g_a3l[(size_t)BH*128*MLM];
__device__ unsigned g_maxbits[2];
__device__ unsigned g_bar_count;
__device__ unsigned g_bar_gen;

__global__ void ln_kernel(const float* __restrict__ x, const float* __restrict__ gamma,
                          const float* __restrict__ beta,
                          __nv_bfloat16* __restrict__ ohi, __nv_bfloat16* __restrict__ olo) {
    int row = blockIdx.x, tid = threadIdx.x;
    const float* xr = x + (size_t)row * D_;
    float v0 = xr[tid], v1 = xr[tid + 256];
    float s = v0 + v1, s2 = v0*v0 + v1*v1;
    #pragma unroll
    for (int o = 16; o > 0; o >>= 1) {
        s  += __shfl_xor_sync(0xffffffffu, s,  o);
        s2 += __shfl_xor_sync(0xffffffffu, s2, o);
    }
    __shared__ float sh[16];
    int w = tid >> 5;
    if ((tid & 31) == 0) { sh[w] = s; sh[w + 8] = s2; }
    __syncthreads();
    if (tid == 0) {
        float a = 0.f, b2 = 0.f;
        #pragma unroll
        for (int i = 0; i < 8; i++) { a += sh[i]; b2 += sh[i + 8]; }
        sh[0] = a; sh[8] = b2;
    }
    __syncthreads();
    float mu  = sh[0] * (1.f / D_);
    float var = sh[8] * (1.f / D_) - mu * mu;
    float inv = rsqrtf(var + 1e-5f);
    size_t base = (size_t)row * D_;
    #pragma unroll
    for (int half = 0; half < 2; half++) {
        int c = tid + half * 256;
        float v = (half == 0 ? v0 : v1);
        float nv = (v - mu) * inv * gamma[c] + beta[c];
        __nv_bfloat16 hi = __float2bfloat16(nv);
        ohi[base + c] = hi;
        olo[base + c] = __float2bfloat16(nv - __bfloat162float(hi));
    }
}

__global__ void tsplit_kernel(const float* __restrict__ W, __nv_bfloat16* __restrict__ Thi,
                              __nv_bfloat16* __restrict__ Tlo, int K, int N) {
    int idx = blockIdx.x * 256 + threadIdx.x;
    if (idx >= K * N) return;
    int k = idx / N, n = idx % N;
    float v = W[idx];
    __nv_bfloat16 hi = __float2bfloat16(v);
    Thi[(size_t)n * K + k] = hi;
    Tlo[(size_t)n * K + k] = __float2bfloat16(v - __bfloat162float(hi));
}
__global__ void vtrans_kernel(const float* __restrict__ v, __nv_bfloat16* __restrict__ vth,
                              __nv_bfloat16* __restrict__ vtl) {
    __shared__ float ts[64][68];
    int bh = blockIdx.y, k0 = blockIdx.x * 64;
    int tid = threadIdx.x;
    const float* vb = v + ((size_t)bh * NTOK + k0) * DH_;
    #pragma unroll
    for (int i = 0; i < 4; i++) {
        int lin = tid + i * 256;
        int r = lin >> 4, c4 = lin & 15;
        *(float4*)&ts[r][c4 * 4] = *(const float4*)(vb + r * 64 + c4 * 4);
    }
    __syncthreads();
    #pragma unroll
    for (int i = 0; i < 16; i++) {
        int lin = tid + i * 256;
        int dh = lin >> 6, ky = lin & 63;
        float val = ts[ky][dh];
        __nv_bfloat16 h = __float2bfloat16(val);
        size_t o = ((size_t)bh * 64 + dh) * NTOK + k0 + ky;
        vth[o] = h;
        vtl[o] = __float2bfloat16(val - __bfloat162float(h));
    }
}

// ---- shared GEMM tile mainloop ----
template<int NPASS>
__device__ __forceinline__ void gemm_tile_main(
        uint32_t sbase, int tid, int wid, int lane, int wm, int wn,
        const __nv_bfloat16* Ahi, const __nv_bfloat16* Alo,
        const __nv_bfloat16* Bhi, const __nv_bfloat16* Blo,
        int kdim, int m0, int n0, float (&acc)[2][8][4])
{
    const __nv_bfloat16* srcs[4] = {Ahi, Alo, Bhi, Blo};
    const int row0s[4] = {m0, m0, n0, n0};
    const int NB = (NPASS == 1) ? 2 : 4;
    int r_ld = tid >> 2, c_ld = tid & 3;
    int nch = kdim >> 5;
    #pragma unroll
    for (int bs = 0; bs < NB; bs++) {
        int bsel = (NPASS == 1) ? bs * 2 : bs;
        #pragma unroll
        for (int i = 0; i < 2; i++)
            cp_async16(sbase + (uint32_t)(bsel * 5120 + (r_ld + i * 64) * 40 + c_ld * 8) * 2,
                       srcs[bsel] + (size_t)(row0s[bsel] + r_ld + i * 64) * kdim + c_ld * 8);
    }
    CP_COMMIT();
    for (int ch = 0; ch < nch; ch++) {
        CP_WAIT0();
        __syncthreads();
        if (ch + 1 < nch) {
            int k0 = (ch + 1) << 5;
            uint32_t nxt_off = (uint32_t)((ch + 1) & 1) * 4 * 5120;
            #pragma unroll
            for (int bs = 0; bs < NB; bs++) {
                int bsel = (NPASS == 1) ? bs * 2 : bs;
                #pragma unroll
                for (int i = 0; i < 2; i++)
                    cp_async16(sbase + (uint32_t)(nxt_off + bsel * 5120 + (r_ld + i * 64) * 40 + c_ld * 8) * 2,
                               srcs[bsel] + (size_t)(row0s[bsel] + r_ld + i * 64) * kdim + k0 + c_ld * 8);
            }
            CP_COMMIT();
        }
        uint32_t stg_off = (uint32_t)(ch & 1) * 4 * 5120;
        #pragma unroll
        for (int ks = 0; ks < 32; ks += 16) {
            uint32_t Ah[2][4], Al[2][4];
            #pragma unroll
            for (int mf = 0; mf < 2; mf++) {
                int row = wm + mf * 16 + (lane & 15);
                int col = ks + ((lane >> 4) << 3);
                ldsm4(Ah[mf], sbase + (uint32_t)(stg_off + row * 40 + col) * 2);
                if (NPASS > 1) ldsm4(Al[mf], sbase + (uint32_t)(stg_off + 5120 + row * 40 + col) * 2);
            }
            #pragma unroll
            for (int p = 0; p < 4; p++) {
                int rowb = wn + (2 * p + (lane >> 4)) * 8 + (lane & 7);
                int colb = ks + ((lane >> 3) & 1) * 8;
                uint32_t Bh4[4], Bl4[4];
                ldsm4(Bh4, sbase + (uint32_t)(stg_off + 2 * 5120 + rowb * 40 + colb) * 2);
                if (NPASS > 1) ldsm4(Bl4, sbase + (uint32_t)(stg_off + 3 * 5120 + rowb * 40 + colb) * 2);
                #pragma unroll
                for (int mf = 0; mf < 2; mf++) {
                    mma_bf16p(acc[mf][2*p],   Ah[mf], Bh4[0], Bh4[1]);
                    mma_bf16p(acc[mf][2*p+1], Ah[mf], Bh4[2], Bh4[3]);
                    if (NPASS > 1) {
                        mma_bf16p(acc[mf][2*p],   Ah[mf], Bl4[0], Bl4[1]);
                        mma_bf16p(acc[mf][2*p+1], Ah[mf], Bl4[2], Bl4[3]);
                        mma_bf16p(acc[mf][2*p],   Al[mf], Bh4[0], Bh4[1]);
                        mma_bf16p(acc[mf][2*p+1], Al[mf], Bh4[2], Bh4[3]);
                    }
                }
            }
        }
    }
    __syncthreads();
}

__device__ __forceinline__ void stage_acc(char* smem, int tid, int wid, int lane, int wm, int wn,
                                          float (&acc)[2][8][4]) {
    float* stg = reinterpret_cast<float*>(smem);
    int r = lane >> 2, c = (lane & 3) * 2;
    #pragma unroll
    for (int mf = 0; mf < 2; mf++)
        #pragma unroll
        for (int nf = 0; nf < 8; nf++) {
            int rr = wm + mf * 16 + r, cc = wn + nf * 8 + c;
            *reinterpret_cast<float2*>(&stg[rr * 132 + cc]) = make_float2(acc[mf][nf][0], acc[mf][nf][1]);
            *reinterpret_cast<float2*>(&stg[(rr + 8) * 132 + cc]) = make_float2(acc[mf][nf][2], acc[mf][nf][3]);
        }
    __syncthreads();
}

// ---- standalone GEMM kernel (modes 0/1) ----
#define TCG_SMEM (2 * 4 * 5120 * 2)
template<int NPASS>
__global__ void __launch_bounds__(256, 2) tc_gemm(
        const __nv_bfloat16* __restrict__ Ahi, const __nv_bfloat16* __restrict__ Alo,
        const __nv_bfloat16* __restrict__ Bhi, const __nv_bfloat16* __restrict__ Blo,
        int K, int mode,
        float* __restrict__ qp, float* __restrict__ kp, float* __restrict__ vp,
        float* __restrict__ Cout, const float* __restrict__ bias, const float* __restrict__ addx,
        __nv_bfloat16* __restrict__ Nhi, __nv_bfloat16* __restrict__ Nlo,
        __nv_bfloat16* __restrict__ Thi, __nv_bfloat16* __restrict__ Tlo)
{
    extern __shared__ __align__(16) char smem[];
    uint32_t sbase = smem_to_u32(smem);
    int tid = threadIdx.x;
    int wid = tid >> 5, lane = tid & 31;
    int wm = (wid & 3) * 32, wn = (wid >> 2) * 64;
    int m0 = blockIdx.y * 128, n0 = blockIdx.x * 128;

    float acc[2][8][4];
    #pragma unroll
    for (int a = 0; a < 2; a++)
        #pragma unroll
        for (int b = 0; b < 8; b++)
            #pragma unroll
            for (int c = 0; c < 4; c++) acc[a][b][c] = 0.f;

    gemm_tile_main<NPASS>(sbase, tid, wid, lane, wm, wn, Ahi, Alo, Bhi, Blo, K, m0, n0, acc);
    stage_acc(smem, tid, wid, lane, wm, wn, acc);
    float* stg = reinterpret_cast<float*>(smem);

    if (mode == 0) {
        #pragma unroll 4
        for (int i = 0; i < 16; i++) {
            int lin = tid + (i << 8);
            int token = lin >> 5, c4 = lin & 31;
            int gn = n0 + (c4 << 2);
            float4 v = *reinterpret_cast<float4*>(&stg[token * 132 + (c4 << 2)]);
            int gmm = m0 + token;
            int b_ = gmm >> 13, n_ = gmm & 8191;
            int sec = gn >> 9, cc = gn & 511, h_ = cc >> 6, dh = cc & 63;
            size_t idx = ((((size_t)b_ * H_ + h_) * NTOK) + n_) * DH_ + dh;
            if (sec == 2) {
                *reinterpret_cast<float4*>(&vp[idx]) = v;
            } else {
                if (sec == 0) { v.x *= 0.125f; v.y *= 0.125f; v.z *= 0.125f; v.w *= 0.125f; }
                float* fp = (sec == 0) ? qp : kp;
                __nv_bfloat16* hp = (sec == 0) ? Nhi : Thi;
                __nv_bfloat16* lp = (sec == 0) ? Nlo : Tlo;
                *reinterpret_cast<float4*>(&fp[idx]) = v;
                float vv[4] = {v.x, v.y, v.z, v.w};
                __nv_bfloat16 hb[4], lb[4];
                #pragma unroll
                for (int t2 = 0; t2 < 4; t2++) {
                    hb[t2] = __float2bfloat16(vv[t2]);
                    lb[t2] = __float2bfloat16(vv[t2] - __bfloat162float(hb[t2]));
                }
                *reinterpret_cast<uint2*>(&hp[idx]) = *reinterpret_cast<uint2*>(hb);
                *reinterpret_cast<uint2*>(&lp[idx]) = *reinterpret_cast<uint2*>(lb);
            }
        }
    } else {
        #pragma unroll 4
        for (int i = 0; i < 16; i++) {
            int lin = tid + (i << 8);
            int token = lin >> 5, c4 = lin & 31;
            int gn = n0 + (c4 << 2);
            int gmm = m0 + token;
            float4 v = *reinterpret_cast<float4*>(&stg[token * 132 + (c4 << 2)]);
            float4 bb = *reinterpret_cast<const float4*>(&bias[gn]);
            float4 xx = *reinterpret_cast<const float4*>(&addx[(size_t)gmm * 512 + gn]);
            v.x += bb.x + xx.x; v.y += bb.y + xx.y; v.z += bb.z + xx.z; v.w += bb.w + xx.w;
            *reinterpret_cast<float4*>(&Cout[(size_t)gmm * 512 + gn]) = v;
        }
    }
}

// ---- persistent pinv + Y ----
__device__ __forceinline__ void grid_barrier() {
    __syncthreads();
    if (threadIdx.x == 0) {
        __threadfence();
        unsigned gen = atomicAdd(&g_bar_gen, 0u);
        unsigned ticket = atomicAdd(&g_bar_count, 1u);
        if (ticket == 127u) {
            g_bar_count = 0u;
            __threadfence();
            atomicAdd(&g_bar_gen, 1u);
        } else {
            while (atomicAdd(&g_bar_gen, 0u) == gen) { }
        }
    }
    __syncthreads();
}

template<int NPASS>
__device__ __forceinline__ void pinv_stage(char* smem, uint32_t sbase,
        const __nv_bfloat16* Ahi, const __nv_bfloat16* Alo,
        const __nv_bfloat16* Bhi, const __nv_bfloat16* Blo,
        __nv_bfloat16* Nhi, __nv_bfloat16* Nlo,
        __nv_bfloat16* Thi, __nv_bfloat16* Tlo,
        float alpha, float diagc, float beta,
        size_t oz, int m0, int n0)
{
    int tid = threadIdx.x;
    int wid = tid >> 5, lane = tid & 31;
    int wm = (wid & 3) * 32, wn = (wid >> 2) * 64;
    float acc[2][8][4];
    #pragma unroll
    for (int a = 0; a < 2; a++)
        #pragma unroll
        for (int b = 0; b < 8; b++)
            #pragma unroll
            for (int c = 0; c < 4; c++) acc[a][b][c] = 0.f;
    gemm_tile_main<NPASS>(sbase, tid, wid, lane, wm, wn,
        Ahi + oz, Alo + oz, Bhi + oz, Blo + oz, MLM, m0, n0, acc);
    stage_acc(smem, tid, wid, lane, wm, wn, acc);
    float* stg = reinterpret_cast<float*>(smem);
    if (Thi) {
        #pragma unroll 4
        for (int i = 0; i < 64; i++) {
            int idx = tid + (i << 8);
            int gn_l = idx >> 7, gm_l = idx & 127;
            int gmm = m0 + gm_l, gn = n0 + gn_l;
            float v = stg[gm_l * 132 + gn_l];
            float t = (gmm == gn ? diagc : 0.f) - beta * v;
            __nv_bfloat16 h = __float2bfloat16(t);
            Thi[oz + (size_t)gn * 256 + gmm] = h;
            Tlo[oz + (size_t)gn * 256 + gmm] = __float2bfloat16(t - __bfloat162float(h));
        }
    }
    if (Nhi) {
        #pragma unroll 4
        for (int i = 0; i < 16; i++) {
            int lin = tid + (i << 8);
            int token = lin >> 5, c4 = lin & 31;
            int gn = n0 + (c4 << 2);
            int gmm = m0 + token;
            float4 v = *reinterpret_cast<float4*>(&stg[token * 132 + (c4 << 2)]);
            float vv[4] = {v.x * alpha, v.y * alpha, v.z * alpha, v.w * alpha};
            __nv_bfloat16 h[4], l2[4];
            #pragma unroll
            for (int t2 = 0; t2 < 4; t2++) {
                h[t2] = __float2bfloat16(vv[t2]);
                l2[t2] = __float2bfloat16(vv[t2] - __bfloat162float(h[t2]));
            }
            *reinterpret_cast<uint2*>(&Nhi[oz + (size_t)gmm * 256 + gn]) = *reinterpret_cast<uint2*>(h);
            *reinterpret_cast<uint2*>(&Nlo[oz + (size_t)gmm * 256 + gn]) = *reinterpret_cast<uint2*>(l2);
        }
    }
    __syncthreads();
}

// Y stage: Y[m, n<64] = Z@A3Vt, transposed-split output to yth/ytl [bh][64][256]
__device__ __forceinline__ void y_stage(char* smem, uint32_t sbase,
        const __nv_bfloat16* Zh, const __nv_bfloat16* Zl,
        const __nv_bfloat16* Bh, const __nv_bfloat16* Bl,
        __nv_bfloat16* yth, __nv_bfloat16* ytl,
        size_t ozA, size_t ozB, size_t ozY, int m0)
{
    int tid = threadIdx.x;
    int wid = tid >> 5, lane = tid & 31;
    int wm = (wid & 3) * 32, wn = (wid >> 2) * 64;
    float acc[2][8][4];
    #pragma unroll
    for (int a = 0; a < 2; a++)
        #pragma unroll
        for (int b = 0; b < 8; b++)
            #pragma unroll
            for (int c = 0; c < 4; c++) acc[a][b][c] = 0.f;
    gemm_tile_main<2>(sbase, tid, wid, lane, wm, wn,
        Zh + ozA, Zl + ozA, Bh + ozB, Bl + ozB, MLM, m0, 0, acc);
    stage_acc(smem, tid, wid, lane, wm, wn, acc);
    float* stg = reinterpret_cast<float*>(smem);
    #pragma unroll 4
    for (int i = 0; i < 64; i++) {
        int idx = tid + (i << 8);
        int gn_l = idx >> 7, gm_l = idx & 127;
        if (gn_l < 64) {
            int gmm = m0 + gm_l;
            float v = stg[gm_l * 132 + gn_l];
            __nv_bfloat16 h = __float2bfloat16(v);
            yth[ozY + (size_t)gn_l * 256 + gmm] = h;
            ytl[ozY + (size_t)gn_l * 256 + gmm] = __float2bfloat16(v - __bfloat162float(h));
        }
    }
    __syncthreads();
}

__global__ void __launch_bounds__(256, 2) pinv_persistent(
        const __nv_bfloat16* __restrict__ Xh, const __nv_bfloat16* __restrict__ Xl,
        __nv_bfloat16* __restrict__ Znh0, __nv_bfloat16* __restrict__ Znl0,
        __nv_bfloat16* __restrict__ Zth0, __nv_bfloat16* __restrict__ Ztl0,
        __nv_bfloat16* __restrict__ XZh, __nv_bfloat16* __restrict__ XZl,
        __nv_bfloat16* __restrict__ WtAh, __nv_bfloat16* __restrict__ WtAl,
        __nv_bfloat16* __restrict__ WtBh, __nv_bfloat16* __restrict__ WtBl,
        const __nv_bfloat16* __restrict__ a3h, const __nv_bfloat16* __restrict__ a3l,
        __nv_bfloat16* __restrict__ yth, __nv_bfloat16* __restrict__ ytl)
{
    extern __shared__ __align__(16) char smem[];
    uint32_t sbase = smem_to_u32(smem);
    int b = blockIdx.x;
    int bh = b >> 2;
    size_t oz = (size_t)bh * 65536;
    int m0 = ((b >> 1) & 1) * 128, n0 = (b & 1) * 128;
    const size_t SB = (size_t)BH * 65536;

    int cur = 0;
    for (int it = 0; it < 6; it++) {
        __nv_bfloat16* Znc = Znh0 + cur * SB; __nv_bfloat16* Znlc = Znl0 + cur * SB;
        __nv_bfloat16* Ztc = Zth0 + cur * SB; __nv_bfloat16* Ztlc = Ztl0 + cur * SB;
        int nxt = cur ^ 1;
        __nv_bfloat16* Znn = Znh0 + nxt * SB; __nv_bfloat16* Znln = Znl0 + nxt * SB;
        __nv_bfloat16* Ztn = Zth0 + nxt * SB; __nv_bfloat16* Ztln = Ztl0 + nxt * SB;
        if (it < 5) {
            pinv_stage<1>(smem, sbase, Xh, Xl, Ztc, Ztlc, XZh, XZl, WtAh, WtAl, 1.f, 7.f, 1.f, oz, m0, n0);
            grid_barrier();
            pinv_stage<1>(smem, sbase, XZh, XZl, WtAh, WtAl, nullptr, nullptr, WtBh, WtBl, 1.f, 15.f, 1.f, oz, m0, n0);
            grid_barrier();
            pinv_stage<1>(smem, sbase, XZh, XZl, WtBh, WtBl, nullptr, nullptr, WtAh, WtAl, 1.f, 13.f, 1.f, oz, m0, n0);
            grid_barrier();
            pinv_stage<1>(smem, sbase, Znc, Znlc, WtAh, WtAl, Znn, Znln, Ztn, Ztln, 0.25f, 0.f, -0.25f, oz, m0, n0);
            grid_barrier();
        } else {
            pinv_stage<2>(smem, sbase, Xh, Xl, Ztc, Ztlc, XZh, XZl, WtAh, WtAl, 1.f, 7.f, 1.f, oz, m0, n0);
            grid_barrier();
            pinv_stage<2>(smem, sbase, XZh, XZl, WtAh, WtAl, nullptr, nullptr, WtBh, WtBl, 1.f, 15.f, 1.f, oz, m0, n0);
            grid_barrier();
            pinv_stage<2>(smem, sbase, XZh, XZl, WtBh, WtBl, nullptr, nullptr, WtAh, WtAl, 1.f, 13.f, 1.f, oz, m0, n0);
            grid_barrier();
            pinv_stage<2>(smem, sbase, Znc, Znlc, WtAh, WtAl, Znn, Znln, nullptr, nullptr, 0.25f, 0.f, -0.25f, oz, m0, n0);
            grid_barrier();
        }
        cur = nxt;
    }
    // Y = Z_final @ A3Vt : only n0==0 blocks participate (N=64)
    if (n0 == 0) {
        y_stage(smem, sbase, Znh0 + cur * SB, Znl0 + cur * SB, a3h, a3l,
                yth, ytl, oz, (size_t)bh * 32768, (size_t)bh * 16384, m0);
    }
}

__global__ void landmark_kernel(const float* __restrict__ q, const float* __restrict__ k,
                                float* __restrict__ ql, float* __restrict__ kl,
                                __nv_bfloat16* __restrict__ qlh, __nv_bfloat16* __restrict__ qll,
                                __nv_bfloat16* __restrict__ klh, __nv_bfloat16* __restrict__ kll) {
    int bh = blockIdx.x, m = blockIdx.y;
    int dh = threadIdx.x;
    size_t base = ((size_t)bh * NTOK + (size_t)m * LSEG) * DH_ + dh;
    float aq = 0.f, ak = 0.f;
    #pragma unroll
    for (int i = 0; i < LSEG; i++) {
        aq += q[base + (size_t)i * DH_];
        ak += k[base + (size_t)i * DH_];
    }
    size_t o = ((size_t)bh * MLM + m) * DH_ + dh;
    float qv = aq * (1.f / LSEG), kv = ak * (1.f / LSEG);
    ql[o] = qv; kl[o] = kv;
    __nv_bfloat16 qh = __float2bfloat16(qv);
    qlh[o] = qh; qll[o] = __float2bfloat16(qv - __bfloat162float(qh));
    __nv_bfloat16 kh = __float2bfloat16(kv);
    klh[o] = kh; kll[o] = __float2bfloat16(kv - __bfloat162float(kh));
}

#define ATTN2_SMEM ((256 * 68 + 32 * 64 + 8) * 4)
__global__ void attn2_kernel(const float* __restrict__ ql, const float* __restrict__ kl,
                             float* __restrict__ X,
                             __nv_bfloat16* __restrict__ Xh, __nv_bfloat16* __restrict__ Xl) {
    extern __shared__ __align__(16) float sh2[];
    float* kls  = sh2;
    float* qs   = sh2 + 256 * 68;
    float* wsum = qs + 32 * 64;
    int bh = blockIdx.x, mt = blockIdx.y;
    int tid = threadIdx.x;
    #pragma unroll
    for (int i = 0; i < 16; i++) {
        int lin = tid + i * 256;
        int r = lin >> 4, c = lin & 15;
        *(float4*)&kls[r * 68 + c * 4] = *(const float4*)&kl[((size_t)bh * MLM + r) * DH_ + c * 4];
    }
    #pragma unroll
    for (int i = 0; i < 2; i++) {
        int lin = tid + i * 256;
        int r = lin >> 4, c = lin & 15;
        *(float4*)&qs[r * 64 + c * 4] = *(const float4*)&ql[((size_t)bh * MLM + mt * 32 + r) * DH_ + c * 4];
    }
    __syncthreads();
    int j = tid, wid = tid >> 5, lane = tid & 31;
    const float* kr = &kls[j * 68];
    for (int ml = 0; ml < 32; ml++) {
        const float* qr = &qs[ml * 64];
        float a0 = 0.f, a1 = 0.f, a2 = 0.f, a3 = 0.f;
        #pragma unroll
        for (int d4 = 0; d4 < 16; d4++) {
            float4 kv = *(const float4*)&kr[d4 * 4];
            float4 qv = *(const float4*)&qr[d4 * 4];
            a0 += qv.x * kv.x; a1 += qv.y * kv.y; a2 += qv.z * kv.z; a3 += qv.w * kv.w;
        }
        float e = fexp(a0 + a1 + a2 + a3);
        float t = e;
        #pragma unroll
        for (int o = 16; o > 0; o >>= 1) t += __shfl_xor_sync(0xffffffffu, t, o);
        if (lane == 0) wsum[wid] = t;
        __syncthreads();
        float S = 0.f;
        #pragma unroll
        for (int w = 0; w < 8; w++) S += wsum[w];
        float val = e * (1.f / S);
        size_t o = ((size_t)bh * MLM + mt * 32 + ml) * MLM + j;
        X[o] = val;
        __nv_bfloat16 h = __float2bfloat16(val);
        Xh[o] = h;
        Xl[o] = __float2bfloat16(val - __bfloat162float(h));
        __syncthreads();
    }
}

__global__ void initmax_kernel(unsigned* mb) { mb[0] = 0u; mb[1] = 0u; g_bar_count = 0u; g_bar_gen = 0u; }
__global__ void rowcol_kernel(const float* __restrict__ X, unsigned* mb) {
    int bh = blockIdx.x, i = threadIdx.x;
    const float* Xm = X + (size_t)bh * MLM * MLM;
    float rs = 0.f, cs = 0.f;
    for (int j = 0; j < MLM; j++) {
        rs += fabsf(Xm[(size_t)i * MLM + j]);
        cs += fabsf(Xm[(size_t)j * MLM + i]);
    }
    #pragma unroll
    for (int o = 16; o > 0; o >>= 1) {
        rs = fmaxf(rs, __shfl_xor_sync(0xffffffffu, rs, o));
        cs = fmaxf(cs, __shfl_xor_sync(0xffffffffu, cs, o));
    }
    __shared__ float shr[8], shc[8];
    int w = i >> 5;
    if ((i & 31) == 0) { shr[w] = rs; shc[w] = cs; }
    __syncthreads();
    if (i == 0) {
        float mr = shr[0], mc = shc[0];
        #pragma unroll
        for (int k2 = 1; k2 < 8; k2++) { mr = fmaxf(mr, shr[k2]); mc = fmaxf(mc, shc[k2]); }
        atomicMax(&mb[0], __float_as_uint(mr));
        atomicMax(&mb[1], __float_as_uint(mc));
    }
}
__global__ void zinit_kernel(const float* __restrict__ X, const unsigned* __restrict__ mb,
                             __nv_bfloat16* __restrict__ Znh, __nv_bfloat16* __restrict__ Znl,
                             __nv_bfloat16* __restrict__ Zth, __nv_bfloat16* __restrict__ Ztl) {
    float inv = 1.f / (__uint_as_float(mb[0]) * __uint_as_float(mb[1]));
    size_t idx = (size_t)blockIdx.x * 256 + threadIdx.x;
    int bh = (int)(idx >> 16);
    int r = (int)((idx >> 8) & 255);
    int c = (int)(idx & 255);
    float tv = X[idx] * inv;
    __nv_bfloat16 th = __float2bfloat16(tv);
    Zth[idx] = th; Ztl[idx] = __float2bfloat16(tv - __bfloat162float(th));
    float nv = X[((size_t)bh << 16) + ((size_t)c << 8) + r] * inv;
    __nv_bfloat16 nh = __float2bfloat16(nv);
    Znh[idx] = nh; Znl[idx] = __float2bfloat16(nv - __bfloat162float(nh));
}

// attn3@v via MMA, cp.async double-buffered k/v tiles.
#define A3_SMEM ((36864 + 2 * 9728) * 2)
__global__ void __launch_bounds__(256, 1) attn3v_mma(
        const __nv_bfloat16* __restrict__ qlh_, const __nv_bfloat16* __restrict__ qll_,
        const __nv_bfloat16* __restrict__ kh_, const __nv_bfloat16* __restrict__ klo_,
        const __nv_bfloat16* __restrict__ vth_, const __nv_bfloat16* __restrict__ vtl_,
        float* __restrict__ Opart, float* __restrict__ denpart)
{
    extern __shared__ __align__(16) __nv_bfloat16 sm3[];
    uint32_t sb = smem_to_u32(sm3);
    int tid = threadIdx.x, wid = tid >> 5, lane = tid & 31;
    int chunk = blockIdx.x, bh = blockIdx.y;
    int key0 = chunk * (NTOK / NCHK);
    {
        size_t qb = (size_t)bh * MLM * DH_;
        #pragma unroll
        for (int i = 0; i < 8; i++) {
            int lin = tid + i * 256;
            int r = lin >> 3, c = lin & 7;
            *(uint4*)(sm3 + r * 72 + c * 8) = *(const uint4*)(qlh_ + qb + r * 64 + c * 8);
            *(uint4*)(sm3 + 18432 + r * 72 + c * 8) = *(const uint4*)(qll_ + qb + r * 64 + c * 8);
        }
    }
    __syncthreads();
    uint32_t Ah[2][4][4], Al[2][4][4];
    #pragma unroll
    for (int mf = 0; mf < 2; mf++) {
        int row = wid * 32 + mf * 16 + (lane & 15);
        #pragma unroll
        for (int ks = 0; ks < 4; ks++) {
            int col = ks * 16 + ((lane >> 4) << 3);
            ldsm4(Ah[mf][ks], sb + (uint32_t)(row * 72 + col) * 2);
            ldsm4(Al[mf][ks], sb + (uint32_t)(18432 + row * 72 + col) * 2);
        }
    }
    float Oacc[2][8][4];
    #pragma unroll
    for (int a = 0; a < 2; a++)
        #pragma unroll
        for (int b = 0; b < 8; b++)
            #pragma unroll
            for (int c = 0; c < 4; c++) Oacc[a][b][c] = 0.f;
    float den[2][2] = {{0.f, 0.f}, {0.f, 0.f}};

    int r_k = tid >> 3, c_k = tid & 7;
    int r_v = tid >> 2, c_v = tid & 3;
    const int NIT = (NTOK / NCHK) / 32;

    {
        int kt0 = key0;
        uint32_t s0 = 36864;
        cp_async16(sb + (uint32_t)(s0 + r_k * 72 + c_k * 8) * 2,
                   kh_ + ((size_t)bh * NTOK + kt0 + r_k) * 64 + c_k * 8);
        cp_async16(sb + (uint32_t)(s0 + 2304 + r_k * 72 + c_k * 8) * 2,
                   klo_ + ((size_t)bh * NTOK + kt0 + r_k) * 64 + c_k * 8);
        cp_async16(sb + (uint32_t)(s0 + 4608 + r_v * 40 + c_v * 8) * 2,
                   vth_ + ((size_t)bh * 64 + r_v) * NTOK + kt0 + c_v * 8);
        cp_async16(sb + (uint32_t)(s0 + 7168 + r_v * 40 + c_v * 8) * 2,
                   vtl_ + ((size_t)bh * 64 + r_v) * NTOK + kt0 + c_v * 8);
    }
    CP_COMMIT();

    for (int t32 = 0; t32 < NIT; t32++) {
        CP_WAIT0();
        __syncthreads();
        if (t32 + 1 < NIT) {
            int kt1 = key0 + (t32 + 1) * 32;
            uint32_t sn = 36864 + (uint32_t)((t32 + 1) & 1) * 9728;
            cp_async16(sb + (uint32_t)(sn + r_k * 72 + c_k * 8) * 2,
                       kh_ + ((size_t)bh * NTOK + kt1 + r_k) * 64 + c_k * 8);
            cp_async16(sb + (uint32_t)(sn + 2304 + r_k * 72 + c_k * 8) * 2,
                       klo_ + ((size_t)bh * NTOK + kt1 + r_k) * 64 + c_k * 8);
            cp_async16(sb + (uint32_t)(sn + 4608 + r_v * 40 + c_v * 8) * 2,
                       vth_ + ((size_t)bh * 64 + r_v) * NTOK + kt1 + c_v * 8);
            cp_async16(sb + (uint32_t)(sn + 7168 + r_v * 40 + c_v * 8) * 2,
                       vtl_ + ((size_t)bh * 64 + r_v) * NTOK + kt1 + c_v * 8);
            CP_COMMIT();
        }
        uint32_t kb = 36864 + (uint32_t)(t32 & 1) * 9728;
        uint32_t klb = kb + 2304, vhb = kb + 4608, vlb = kb + 7168;
        float S[2][4][4];
        #pragma unroll
        for (int a = 0; a < 2; a++)
            #pragma unroll
            for (int b = 0; b < 4; b++)
                #pragma unroll
                for (int c = 0; c < 4; c++) S[a][b][c] = 0.f;
        #pragma unroll
        for (int ks = 0; ks < 4; ks++) {
            #pragma unroll
            for (int np = 0; np < 2; np++) {
                int row = np * 16 + ((lane >> 4) & 1) * 8 + (lane & 7);
                int col = ks * 16 + ((lane >> 3) & 1) * 8;
                uint32_t bh4[4], bl4[4];
                ldsm4(bh4, sb + (uint32_t)(kb + row * 72 + col) * 2);
                ldsm4(bl4, sb + (uint32_t)(klb + row * 72 + col) * 2);
                #pragma unroll
                for (int mf = 0; mf < 2; mf++) {
                    mma_bf16p(S[mf][2*np],   Ah[mf][ks], bh4[0], bh4[1]);
                    mma_bf16p(S[mf][2*np],   Ah[mf][ks], bl4[0], bl4[1]);
                    mma_bf16p(S[mf][2*np],   Al[mf][ks], bh4[0], bh4[1]);
                    mma_bf16p(S[mf][2*np+1], Ah[mf][ks], bh4[2], bh4[3]);
                    mma_bf16p(S[mf][2*np+1], Ah[mf][ks], bl4[2], bl4[3]);
                    mma_bf16p(S[mf][2*np+1], Al[mf][ks], bh4[2], bh4[3]);
                }
            }
        }
        #pragma unroll
        for (int kt = 0; kt < 2; kt++) {
            uint32_t pah[2][4], pal[2][4];
            #pragma unroll
            for (int mf = 0; mf < 2; mf++) {
                float e[8];
                #pragma unroll
                for (int j = 0; j < 4; j++) { e[j] = fexp(S[mf][2*kt][j]); e[4+j] = fexp(S[mf][2*kt+1][j]); }
                den[mf][0] += e[0] + e[1] + e[4] + e[5];
                den[mf][1] += e[2] + e[3] + e[6] + e[7];
                #pragma unroll
                for (int j = 0; j < 4; j++) {
                    __nv_bfloat162 h2 = __floats2bfloat162_rn(e[2*j], e[2*j+1]);
                    pah[mf][j] = *(uint32_t*)&h2;
                    float r0 = e[2*j]   - __bfloat162float(__low2bfloat16(h2));
                    float r1 = e[2*j+1] - __bfloat162float(__high2bfloat16(h2));
                    __nv_bfloat162 l2 = __floats2bfloat162_rn(r0, r1);
                    pal[mf][j] = *(uint32_t*)&l2;
                }
            }
            #pragma unroll
            for (int np = 0; np < 4; np++) {
                int row = np * 16 + ((lane >> 4) & 1) * 8 + (lane & 7);
                int col = kt * 16 + ((lane >> 3) & 1) * 8;
                uint32_t vh4[4], vl4[4];
                ldsm4(vh4, sb + (uint32_t)(vhb + row * 40 + col) * 2);
                ldsm4(vl4, sb + (uint32_t)(vlb + row * 40 + col) * 2);
                #pragma unroll
                for (int mf = 0; mf < 2; mf++) {
                    mma_bf16p(Oacc[mf][2*np],   pah[mf], vh4[0], vh4[1]);
                    mma_bf16p(Oacc[mf][2*np],   pah[mf], vl4[0], vl4[1]);
                    mma_bf16p(Oacc[mf][2*np],   pal[mf], vh4[0], vh4[1]);
                    mma_bf16p(Oacc[mf][2*np+1], pah[mf], vh4[2], vh4[3]);
                    mma_bf16p(Oacc[mf][2*np+1], pah[mf], vl4[2], vl4[3]);
                    mma_bf16p(Oacc[mf][2*np+1], pal[mf], vh4[2], vh4[3]);
                }
            }
        }
    }
    #pragma unroll
    for (int mf = 0; mf < 2; mf++)
        #pragma unroll
        for (int j = 0; j < 2; j++) {
            den[mf][j] += __shfl_xor_sync(0xffffffffu, den[mf][j], 1);
            den[mf][j] += __shfl_xor_sync(0xffffffffu, den[mf][j], 2);
        }
    int g = lane >> 2, t = lane & 3;
    size_t ob = ((size_t)chunk * BH + bh) * MLM * 64;
    #pragma unroll
    for (int mf = 0; mf < 2; mf++) {
        int lm0 = wid * 32 + mf * 16 + g;
        #pragma unroll
        for (int nf = 0; nf < 8; nf++) {
            int c = nf * 8 + t * 2;
            *(float2*)&Opart[ob + (size_t)lm0 * 64 + c] = make_float2(Oacc[mf][nf][0], Oacc[mf][nf][1]);
            *(float2*)&Opart[ob + (size_t)(lm0 + 8) * 64 + c] = make_float2(Oacc[mf][nf][2], Oacc[mf][nf][3]);
        }
        if (t == 0) {
            denpart[((size_t)chunk * BH + bh) * MLM + lm0] = den[mf][0];
            denpart[((size_t)chunk * BH + bh) * MLM + lm0 + 8] = den[mf][1];
        }
    }
}

// reduce partials -> transposed bf16 split A3Vt [bh][128][256] (rows>=64 zero)
__global__ void a3v_reduce(const float* __restrict__ Opart, const float* __restrict__ denpart,
                           __nv_bfloat16* __restrict__ a3h, __nv_bfloat16* __restrict__ a3l) {
    int idx = blockIdx.x * 256 + threadIdx.x;          // over BH*256*64
    int bh = idx >> 14, lm = (idx >> 6) & 255, dh = idx & 63;
    float s = 0.f, d = 0.f;
    #pragma unroll
    for (int c = 0; c < NCHK; c++) {
        s += Opart[((size_t)c * BH + bh) * 16384 + (idx & 16383)];
        d += denpart[((size_t)c * BH + bh) * 256 + lm];
    }
    float val = s / d;
    size_t o = (size_t)bh * 32768 + (size_t)dh * 256 + lm;
    __nv_bfloat16 h = __float2bfloat16(val);
    a3h[o] = h;
    a3l[o] = __float2bfloat16(val - __bfloat162float(h));
    // zero the padding row dh+64
    size_t oz = (size_t)bh * 32768 + (size_t)(dh + 64) * 256 + lm;
    a3h[oz] = __float2bfloat16(0.f);
    a3l[oz] = __float2bfloat16(0.f);
}

// attn1 + conv + osplit fused; v-halo load overlapped with MMA via cp.async groups
#define A1V_OFF  89088
#define A1KW_OFF (178176 + 43520)
#define A1_SMEM  (178176 + 43520 + 256)
__global__ void __launch_bounds__(256, 1) attn1_mma(
        const __nv_bfloat16* __restrict__ qh_, const __nv_bfloat16* __restrict__ qlo_,
        const __nv_bfloat16* __restrict__ klh_, const __nv_bfloat16* __restrict__ kll_,
        const __nv_bfloat16* __restrict__ yth_, const __nv_bfloat16* __restrict__ ytl_,
        const float* __restrict__ v_, const float* __restrict__ ker,
        __nv_bfloat16* __restrict__ Ohi, __nv_bfloat16* __restrict__ Olo)
{
    extern __shared__ __align__(16) __nv_bfloat16 sm1[];
    uint32_t sb = smem_to_u32(sm1);
    float* vs = reinterpret_cast<float*>(sm1 + A1V_OFF);
    float* kw = reinterpret_cast<float*>((char*)sm1 + A1KW_OFF);
    int tid = threadIdx.x, wid = tid >> 5, lane = tid & 31;
    int bh = blockIdx.y;
    int b = bh >> 3, h = bh & 7;
    {
        size_t kb = (size_t)bh * MLM * DH_;
        #pragma unroll
        for (int i = 0; i < 8; i++) {
            int lin = tid + i * 256;
            int r = lin >> 3, c = lin & 7;
            *(uint4*)(sm1 + 18432 + r * 72 + c * 8) = *(const uint4*)(klh_ + kb + r * 64 + c * 8);
            *(uint4*)(sm1 + 36864 + r * 72 + c * 8) = *(const uint4*)(kll_ + kb + r * 64 + c * 8);
        }
        size_t yb = (size_t)bh * 64 * MLM;
        #pragma unroll
        for (int i = 0; i < 8; i++) {
            int lin = tid + i * 256;
            int r = lin >> 5, c = lin & 31;
            *(uint4*)(sm1 + 55296 + r * 264 + c * 8) = *(const uint4*)(yth_ + yb + r * 256 + c * 8);
            *(uint4*)(sm1 + 72192 + r * 264 + c * 8) = *(const uint4*)(ytl_ + yb + r * 256 + c * 8);
        }
        if (tid < KER_) kw[tid] = ker[h * KER_ + tid];
    }
    const float* vb = v_ + ((size_t)b * H_ + h) * NTOK * DH_;

    for (int tt = 0; tt < A1_TPB; tt++) {
        int tile0 = (blockIdx.x * A1_TPB + tt) * 128;
        __syncthreads();
        {
            size_t qb = ((size_t)bh * NTOK + tile0) * DH_;
            #pragma unroll
            for (int i = 0; i < 4; i++) {
                int lin = tid + i * 256;
                int r = lin >> 3, c = lin & 7;
                cp_async16(sb + (uint32_t)(r * 72 + c * 8) * 2, qh_ + qb + (size_t)r * 64 + c * 8);
                cp_async16(sb + (uint32_t)(9216 + r * 72 + c * 8) * 2, qlo_ + qb + (size_t)r * 64 + c * 8);
            }
            CP_COMMIT();
            #pragma unroll
            for (int i = 0; i < 10; i++) {
                int f4 = tid + i * 256;
                int row = f4 >> 4, c4 = f4 & 15;
                int n = tile0 - 16 + row;
                if (n >= 0 && n < NTOK)
                    cp_async16(sb + (uint32_t)(A1V_OFF * 2 + (row * 68 + c4 * 4) * 4),
                               vb + (size_t)n * DH_ + c4 * 4);
                else
                    *(float4*)&vs[row * 68 + c4 * 4] = make_float4(0.f, 0.f, 0.f, 0.f);
            }
            CP_COMMIT();
        }
        CP_WAIT1();
        __syncthreads();
        uint32_t Ah[4][4], Al[4][4];
        {
            int row = wid * 16 + (lane & 15);
            #pragma unroll
            for (int ks = 0; ks < 4; ks++) {
                int col = ks * 16 + ((lane >> 4) << 3);
                ldsm4(Ah[ks], sb + (uint32_t)(row * 72 + col) * 2);
                ldsm4(Al[ks], sb + (uint32_t)(9216 + row * 72 + col) * 2);
            }
        }
        float Oacc[8][4];
        #pragma unroll
        for (int bb = 0; bb < 8; bb++)
            #pragma unroll
            for (int c = 0; c < 4; c++) Oacc[bb][c] = 0.f;
        float dlo = 0.f, dhi = 0.f;

        #pragma unroll
        for (int half = 0; half < 2; half++) {
            int lmb = half * 128;
            float S[16][4];
            #pragma unroll
            for (int bb = 0; bb < 16; bb++)
                #pragma unroll
                for (int c = 0; c < 4; c++) S[bb][c] = 0.f;
            #pragma unroll
            for (int ks = 0; ks < 4; ks++) {
                #pragma unroll
                for (int np = 0; np < 8; np++) {
                    int row = lmb + np * 16 + ((lane >> 4) & 1) * 8 + (lane & 7);
                    int col = ks * 16 + ((lane >> 3) & 1) * 8;
                    uint32_t bh4[4], bl4[4];
                    ldsm4(bh4, sb + (uint32_t)(18432 + row * 72 + col) * 2);
                    ldsm4(bl4, sb + (uint32_t)(36864 + row * 72 + col) * 2);
                    mma_bf16p(S[2*np],   Ah[ks], bh4[0], bh4[1]);
                    mma_bf16p(S[2*np],   Ah[ks], bl4[0], bl4[1]);
                    mma_bf16p(S[2*np],   Al[ks], bh4[0], bh4[1]);
                    mma_bf16p(S[2*np+1], Ah[ks], bh4[2], bh4[3]);
                    mma_bf16p(S[2*np+1], Ah[ks], bl4[2], bl4[3]);
                    mma_bf16p(S[2*np+1], Al[ks], bh4[2], bh4[3]);
                }
            }
            #pragma unroll
            for (int kt = 0; kt < 8; kt++) {
                float e[8];
                #pragma unroll
                for (int j = 0; j < 4; j++) { e[j] = fexp(S[2*kt][j]); e[4+j] = fexp(S[2*kt+1][j]); }
                dlo += e[0] + e[1] + e[4] + e[5];
                dhi += e[2] + e[3] + e[6] + e[7];
                uint32_t pah[4], pal[4];
                #pragma unroll
                for (int j = 0; j < 4; j++) {
                    __nv_bfloat162 h2 = __floats2bfloat162_rn(e[2*j], e[2*j+1]);
                    pah[j] = *(uint32_t*)&h2;
                    float r0 = e[2*j]   - __bfloat162float(__low2bfloat16(h2));
                    float r1 = e[2*j+1] - __bfloat162float(__high2bfloat16(h2));
                    __nv_bfloat162 l2 = __floats2bfloat162_rn(r0, r1);
                    pal[j] = *(uint32_t*)&l2;
                }
                #pragma unroll
                for (int np = 0; np < 4; np++) {
                    int row = np * 16 + ((lane >> 4) & 1) * 8 + (lane & 7);
                    int col = lmb + kt * 16 + ((lane >> 3) & 1) * 8;
                    uint32_t yh4[4], yl4[4];
                    ldsm4(yh4, sb + (uint32_t)(55296 + row * 264 + col) * 2);
                    ldsm4(yl4, sb + (uint32_t)(72192 + row * 264 + col) * 2);
                    mma_bf16p(Oacc[2*np],   pah, yh4[0], yh4[1]);
                    mma_bf16p(Oacc[2*np],   pah, yl4[0], yl4[1]);
                    mma_bf16p(Oacc[2*np],   pal, yh4[0], yh4[1]);
                    mma_bf16p(Oacc[2*np+1], pah, yh4[2], yh4[3]);
                    mma_bf16p(Oacc[2*np+1], pah, yl4[2], yl4[3]);
                    mma_bf16p(Oacc[2*np+1], pal, yh4[2], yh4[3]);
                }
            }
        }
        CP_WAIT0();
        __syncthreads();
        dlo += __shfl_xor_sync(0xffffffffu, dlo, 1);
        dlo += __shfl_xor_sync(0xffffffffu, dlo, 2);
        dhi += __shfl_xor_sync(0xffffffffu, dhi, 1);
        dhi += __shfl_xor_sync(0xffffffffu, dhi, 2);
        float ilo = 1.f / dlo, ihi = 1.f / dhi;
        int g = lane >> 2, t = lane & 3;
        int tok0 = tile0 + wid * 16 + g;
        int r0 = wid * 16 + g;
        size_t ob = ((size_t)b * NTOK + tok0) * D_ + h * DH_;
        #pragma unroll
        for (int nf = 0; nf < 8; nf++) {
            int c = nf * 8 + t * 2;
            float cv00 = 0.f, cv01 = 0.f, cv10 = 0.f, cv11 = 0.f;
            #pragma unroll
            for (int tap = 0; tap < KER_; tap++) {
                float w = kw[tap];
                cv00 += w * vs[(r0 + tap) * 68 + c];
                cv01 += w * vs[(r0 + tap) * 68 + c + 1];
                cv10 += w * vs[(r0 + 8 + tap) * 68 + c];
                cv11 += w * vs[(r0 + 8 + tap) * 68 + c + 1];
            }
            float o00 = Oacc[nf][0] * ilo + cv00;
            float o01 = Oacc[nf][1] * ilo + cv01;
            float o10 = Oacc[nf][2] * ihi + cv10;
            float o11 = Oacc[nf][3] * ihi + cv11;
            __nv_bfloat162 h0 = __floats2bfloat162_rn(o00, o01);
            __nv_bfloat162 l0 = __floats2bfloat162_rn(o00 - __bfloat162float(__low2bfloat16(h0)),
                                                      o01 - __bfloat162float(__high2bfloat16(h0)));
            *(uint32_t*)&Ohi[ob + c] = *(uint32_t*)&h0;
            *(uint32_t*)&Olo[ob + c] = *(uint32_t*)&l0;
            __nv_bfloat162 h1 = __floats2bfloat162_rn(o10, o11);
            __nv_bfloat162 l1 = __floats2bfloat162_rn(o10 - __bfloat162float(__low2bfloat16(h1)),
                                                      o11 - __bfloat162float(__high2bfloat16(h1)));
            *(uint32_t*)&Ohi[ob + (size_t)8 * D_ + c] = *(uint32_t*)&h1;
            *(uint32_t*)&Olo[ob + (size_t)8 * D_ + c] = *(uint32_t*)&l1;
        }
    }
}

extern "C" void kernel_launch(void* const* d_in, const int* in_sizes, int n_in,
                              void* d_out, int out_size) {
    const float* x      = (const float*)d_in[0];
    const float* gamma  = (const float*)d_in[1];
    const float* beta   = (const float*)d_in[2];
    const float* w_qkv  = (const float*)d_in[3];
    const float* res_k  = (const float*)d_in[4];
    const float* w_out  = (const float*)d_in[5];
    const float* b_out  = (const float*)d_in[6];
    float* out = (float*)d_out;

    __nv_bfloat16 *nh, *nl, *wqh, *wql, *woh, *wol, *Oh, *Ol, *Xh, *Xl;
    __nv_bfloat16 *Znh, *Znl, *Zth, *Ztl, *XZh, *XZl, *WtAh, *WtAl, *WtBh, *WtBl;
    __nv_bfloat16 *qbh, *qbl, *kbh, *kbl, *vth, *vtl, *qlh, *qll, *klh, *kll, *yth, *ytl, *a3h, *a3l;
    float *q, *k, *v, *ql, *kl, *X, *Opart, *dpart;
    unsigned* mb;
    cudaGetSymbolAddress((void**)&nh, g_nh);
    cudaGetSymbolAddress((void**)&nl, g_nl);
    cudaGetSymbolAddress((void**)&wqh, g_wqh);
    cudaGetSymbolAddress((void**)&wql, g_wql);
    cudaGetSymbolAddress((void**)&woh, g_woh);
    cudaGetSymbolAddress((void**)&wol, g_wol);
    cudaGetSymbolAddress((void**)&Oh, g_Oh);
    cudaGetSymbolAddress((void**)&Ol, g_Ol);
    cudaGetSymbolAddress((void**)&Xh, g_Xh);
    cudaGetSymbolAddress((void**)&Xl, g_Xl);
    cudaGetSymbolAddress((void**)&Znh, g_Znh);
    cudaGetSymbolAddress((void**)&Znl, g_Znl);
    cudaGetSymbolAddress((void**)&Zth, g_Zth);
    cudaGetSymbolAddress((void**)&Ztl, g_Ztl);
    cudaGetSymbolAddress((void**)&XZh, g_XZh);
    cudaGetSymbolAddress((void**)&XZl, g_XZl);
    cudaGetSymbolAddress((void**)&WtAh, g_WtAh);
    cudaGetSymbolAddress((void**)&WtAl, g_WtAl);
    cudaGetSymbolAddress((void**)&WtBh, g_WtBh);
    cudaGetSymbolAddress((void**)&WtBl, g_WtBl);
    cudaGetSymbolAddress((void**)&q,  g_q);
    cudaGetSymbolAddress((void**)&k,  g_k);
    cudaGetSymbolAddress((void**)&v,  g_v);
    cudaGetSymbolAddress((void**)&qbh, g_qbh);
    cudaGetSymbolAddress((void**)&qbl, g_qbl);
    cudaGetSymbolAddress((void**)&kbh, g_kbh);
    cudaGetSymbolAddress((void**)&kbl, g_kbl);
    cudaGetSymbolAddress((void**)&vth, g_vth);
    cudaGetSymbolAddress((void**)&vtl, g_vtl);
    cudaGetSymbolAddress((void**)&ql, g_ql);
    cudaGetSymbolAddress((void**)&kl, g_kl);
    cudaGetSymbolAddress((void**)&qlh, g_qlh);
    cudaGetSymbolAddress((void**)&qll, g_qll);
    cudaGetSymbolAddress((void**)&klh, g_klh);
    cudaGetSymbolAddress((void**)&kll, g_kll);
    cudaGetSymbolAddress((void**)&yth, g_yth);
    cudaGetSymbolAddress((void**)&ytl, g_ytl);
    cudaGetSymbolAddress((void**)&a3h, g_a3h);
    cudaGetSymbolAddress((void**)&a3l, g_a3l);
    cudaGetSymbolAddress((void**)&X,  g_X);
    cudaGetSymbolAddress((void**)&Opart, g_Opart);
    cudaGetSymbolAddress((void**)&dpart, g_dpart);
    cudaGetSymbolAddress((void**)&mb, g_maxbits);

    cudaFuncSetAttribute(attn2_kernel, cudaFuncAttributeMaxDynamicSharedMemorySize, ATTN2_SMEM);
    cudaFuncSetAttribute(tc_gemm<2>, cudaFuncAttributeMaxDynamicSharedMemorySize, TCG_SMEM);
    cudaFuncSetAttribute(pinv_persistent, cudaFuncAttributeMaxDynamicSharedMemorySize, TCG_SMEM);
    cudaFuncSetAttribute(attn3v_mma, cudaFuncAttributeMaxDynamicSharedMemorySize, A3_SMEM);
    cudaFuncSetAttribute(attn1_mma, cudaFuncAttributeMaxDynamicSharedMemorySize, A1_SMEM);

    ln_kernel<<<B_ * NTOK, 256>>>(x, gamma, beta, nh, nl);
    tsplit_kernel<<<(D_ * 3 * D_ + 255) / 256, 256>>>(w_qkv, wqh, wql, D_, 3 * D_);
    tsplit_kernel<<<(D_ * D_ + 255) / 256, 256>>>(w_out, woh, wol, D_, D_);

    tc_gemm<2><<<dim3(12, 256, 1), 256, TCG_SMEM>>>(nh, nl, wqh, wql, D_, 0,
        q, k, v, nullptr, nullptr, nullptr, qbh, qbl, kbh, kbl);

    vtrans_kernel<<<dim3(NTOK / 64, BH), 256>>>(v, vth, vtl);
    landmark_kernel<<<dim3(BH, MLM), 64>>>(q, k, ql, kl, qlh, qll, klh, kll);

    attn2_kernel<<<dim3(BH, 8), 256, ATTN2_SMEM>>>(ql, kl, X, Xh, Xl);
    initmax_kernel<<<1, 1>>>(mb);
    rowcol_kernel<<<BH, 256>>>(X, mb);
    zinit_kernel<<<8192, 256>>>(X, mb, Znh, Znl, Zth, Ztl);

    // attn3@v first (A3Vt splits ready before pinv's Y stage)
    attn3v_mma<<<dim3(NCHK, BH), 256, A3_SMEM>>>(qlh, qll, kbh, kbl, vth, vtl, Opart, dpart);
    a3v_reduce<<<2048, 256>>>(Opart, dpart, a3h, a3l);

    // pinv Newton + fused Y = Z@A3Vt (writes yth/ytl)
    pinv_persistent<<<128, 256, TCG_SMEM>>>(Xh, Xl, Znh, Znl, Zth, Ztl,
        XZh, XZl, WtAh, WtAl, WtBh, WtBl, a3h, a3l, yth, ytl);

    attn1_mma<<<dim3(NTOK / 128 / A1_TPB, BH), 256, A1_SMEM>>>(
        qbh, qbl, klh, kll, yth, ytl, v, res_k, Oh, Ol);

    tc_gemm<2><<<dim3(4, 256, 1), 256, TCG_SMEM>>>(Oh, Ol, woh, wol, D_, 1,
        nullptr, nullptr, nullptr, out, b_out, x, nullptr, nullptr, nullptr, nullptr);
}